// round 13
// baseline (speedup 1.0000x reference)
#include <cuda_runtime.h>
#include <cuda_fp16.h>
#include <cstdint>

#define B_ 8
#define C_ 256
#define D_ 32
#define N_ 4096
#define QTILE 64
#define KTILE 64
#define NTILES (N_ / KTILE)
#define THREADS 256

// attn smem byte offsets
#define SM_Q  0                         // Q hi/lo: 2 x 64 x 64B (SW64) = 8192
#define SM_K  8192                      // K[buf][hl]: 4 x 4096 (SW64)  = 16384
#define SM_V  24576                     // V[buf]: 2 x 32768 (SW128)    = 65536
#define SM_P  90112                     // P[buf]: 2 x 8192 (SW128)     = 16384
#define SM_PM 106496                    // pmax[64][4] floats           = 1024
#define SM_LS 107520                    // lsum[64][4] floats           = 1024
#define SM_LR 108544                    // lrecip[64] floats            = 256
#define SM_TOTAL 108800

// qkv_mma smem: W [buf2][hl2][4KB] + X [buf2][hl2][16KB]
#define QSW 0
#define QSX 16384
#define QS_TOTAL 81920

// ---------------------------------------------------------------------------
// scratch (allocation-free rule: device globals)
// ---------------------------------------------------------------------------
__device__ __half g_qh[(size_t)B_ * N_ * D_];
__device__ __half g_ql[(size_t)B_ * N_ * D_];
__device__ __half g_kh[(size_t)B_ * N_ * D_];
__device__ __half g_kl[(size_t)B_ * N_ * D_];
__device__ __half g_v [(size_t)B_ * C_ * N_];
__device__ __half g_xh[(size_t)B_ * C_ * N_];   // x split hi [b][c][n]
__device__ __half g_xl[(size_t)B_ * C_ * N_];   // x split lo
__device__ __half g_wh[320 * 256];              // [Wq;Wk;Wv] split hi
__device__ __half g_wl[320 * 256];

__device__ __forceinline__ uint32_t smem_u32(const void* p) {
    uint32_t a;
    asm("{ .reg .u64 t; cvta.to.shared.u64 t, %1; cvt.u32.u64 %0, t; }" : "=r"(a) : "l"(p));
    return a;
}
__device__ __forceinline__ void ldsm4(uint32_t* r, uint32_t addr) {
    asm volatile("ldmatrix.sync.aligned.m8n8.x4.shared.b16 {%0,%1,%2,%3}, [%4];"
                 : "=r"(r[0]), "=r"(r[1]), "=r"(r[2]), "=r"(r[3]) : "r"(addr));
}
__device__ __forceinline__ void ldsm4t(uint32_t* r, uint32_t addr) {
    asm volatile("ldmatrix.sync.aligned.m8n8.x4.trans.shared.b16 {%0,%1,%2,%3}, [%4];"
                 : "=r"(r[0]), "=r"(r[1]), "=r"(r[2]), "=r"(r[3]) : "r"(addr));
}
__device__ __forceinline__ void mma_f16(float* c, const uint32_t* a, uint32_t b0, uint32_t b1) {
    asm volatile("mma.sync.aligned.m16n8k16.row.col.f32.f16.f16.f32 "
                 "{%0,%1,%2,%3}, {%4,%5,%6,%7}, {%8,%9}, {%0,%1,%2,%3};"
                 : "+f"(c[0]), "+f"(c[1]), "+f"(c[2]), "+f"(c[3])
                 : "r"(a[0]), "r"(a[1]), "r"(a[2]), "r"(a[3]), "r"(b0), "r"(b1));
}
__device__ __forceinline__ void cpa16(uint32_t dst, const void* src) {
    asm volatile("cp.async.cg.shared.global [%0], [%1], 16;" :: "r"(dst), "l"(src));
}
#define CP_COMMIT() asm volatile("cp.async.commit_group;" ::: "memory")
#define CP_WAIT(n)  asm volatile("cp.async.wait_group %0;" :: "n"(n) : "memory")

// swizzles: 64B rows (Q/K/W) and 128B rows (V/P)
__device__ __forceinline__ uint32_t sw64(int row, int u)  { return row * 64  + ((u ^ ((row >> 1) & 3)) << 4); }
__device__ __forceinline__ uint32_t sw128(int row, int u) { return row * 128 + ((u ^ (row & 7)) << 4); }

// ldmatrix x4 address helpers
__device__ __forceinline__ uint32_t a64(uint32_t base, int row0, int k16, int lane) {
    int lr = lane & 7, grp = lane >> 3;
    return base + sw64(row0 + lr + (grp & 1) * 8, k16 + (grp >> 1));
}
__device__ __forceinline__ uint32_t b64(uint32_t base, int row0, int k16, int lane) {
    int lr = lane & 7, grp = lane >> 3;
    return base + sw64(row0 + lr + (grp >> 1) * 8, k16 + (grp & 1));
}
__device__ __forceinline__ uint32_t a128(uint32_t base, int row0, int k16, int lane) {
    int lr = lane & 7, grp = lane >> 3;
    return base + sw128(row0 + lr + (grp & 1) * 8, k16 + (grp >> 1));
}
__device__ __forceinline__ uint32_t b128(uint32_t base, int row0, int k16, int lane) {
    int lr = lane & 7, grp = lane >> 3;
    return base + sw128(row0 + lr + (grp >> 1) * 8, k16 + (grp & 1));
}
// B-fragment (trans) from X stored [k][n] (512B rows, k-XOR swizzle on 16B units)
__device__ __forceinline__ uint32_t bxt(uint32_t base, int k0, int n0, int lane) {
    int lr = lane & 7, grp = lane >> 3;
    int k  = k0 + lr + (grp & 1) * 8;
    int un = (n0 >> 3) + (grp >> 1);
    return base + (k * 32 + (un ^ (k & 7))) * 16;
}
__device__ __forceinline__ uint32_t h2pack(float a, float b) {
    __half2 h = __floats2half2_rn(a, b);
    return *reinterpret_cast<uint32_t*>(&h);
}

// ---------------------------------------------------------------------------
// split kernel: x -> g_xh/g_xl, [Wq;Wk;Wv] -> g_wh/g_wl (fp16 hi/lo)
// ---------------------------------------------------------------------------
__global__ __launch_bounds__(256) void split_kernel(
    const float* __restrict__ x,
    const float* __restrict__ Wq, const float* __restrict__ Wk,
    const float* __restrict__ Wv)
{
    const int bid = blockIdx.x;
    const int t   = threadIdx.x;
    if (bid < 4096) {
        size_t base = (size_t)bid * 2048 + (size_t)t * 8;
        float4 v0 = *(const float4*)(x + base);
        float4 v1 = *(const float4*)(x + base + 4);
        float vv[8] = {v0.x, v0.y, v0.z, v0.w, v1.x, v1.y, v1.z, v1.w};
        __half h[8], l[8];
#pragma unroll
        for (int i = 0; i < 8; i++) {
            h[i] = __float2half_rn(vv[i]);
            l[i] = __float2half_rn(vv[i] - __half2float(h[i]));
        }
        *(uint4*)(g_xh + base) = *(uint4*)h;
        *(uint4*)(g_xl + base) = *(uint4*)l;
    } else {
        int idx = (bid - 4096) * 2048 + t * 8;
        if (idx < 320 * 256) {
            int row = idx >> 8, col = idx & 255;
            const float* src;
            if (row < 32)       src = Wq + row * 256 + col;
            else if (row < 64)  src = Wk + (row - 32) * 256 + col;
            else                src = Wv + (row - 64) * 256 + col;
            float4 v0 = *(const float4*)(src);
            float4 v1 = *(const float4*)(src + 4);
            float vv[8] = {v0.x, v0.y, v0.z, v0.w, v1.x, v1.y, v1.z, v1.w};
            __half h[8], l[8];
#pragma unroll
            for (int i = 0; i < 8; i++) {
                h[i] = __float2half_rn(vv[i]);
                l[i] = __float2half_rn(vv[i] - __half2float(h[i]));
            }
            *(uint4*)(g_wh + idx) = *(uint4*)h;
            *(uint4*)(g_wl + idx) = *(uint4*)l;
        }
    }
}

// ---------------------------------------------------------------------------
// qkv via tensor cores (unchanged): Y = W @ X + bias, 3-term fp16.
// ---------------------------------------------------------------------------
__global__ __launch_bounds__(256, 2) void qkv_mma(
    const float* __restrict__ bq, const float* __restrict__ bk,
    const float* __restrict__ bv)
{
    extern __shared__ char smem[];
    const uint32_t sb = smem_u32(smem);
    const int t    = threadIdx.x;
    const int w    = t >> 5;
    const int lane = t & 31;
    const int g    = lane >> 2;
    const int tig  = lane & 3;
    const int n0   = blockIdx.x * 256;
    const int row0 = blockIdx.y * 64;
    const int b    = blockIdx.z;
    const int mqw  = (w & 1) * 32;
    const int nw   = (w >> 1) * 64;

    {
        const int k0 = 0;
#pragma unroll
        for (int it = 0; it < 2; it++) {
            int cw = it * THREADS + t;
            int hl = cw >> 8, idx = cw & 255, r = idx >> 2, u = idx & 3;
            const __half* src = (hl ? g_wl : g_wh) + (row0 + r) * 256 + k0 + u * 8;
            cpa16(sb + QSW + hl * 4096 + sw64(r, u), src);
        }
#pragma unroll
        for (int it = 0; it < 8; it++) {
            int cx = it * THREADS + t;
            int hl = cx >> 10, idx = cx & 1023, k = idx >> 5, u = idx & 31;
            const __half* src = (hl ? g_xl : g_xh) + ((size_t)(b * 256 + k0 + k)) * N_ + n0 + u * 8;
            cpa16(sb + QSX + hl * 16384 + (k * 32 + (u ^ (k & 7))) * 16, src);
        }
        CP_COMMIT();
    }

    float o[2][8][4];
#pragma unroll
    for (int mb = 0; mb < 2; mb++)
#pragma unroll
        for (int nb = 0; nb < 8; nb++)
#pragma unroll
            for (int r = 0; r < 4; r++) o[mb][nb][r] = 0.f;

    for (int ck = 0; ck < 8; ck++) {
        const int buf = ck & 1;
        __syncthreads();
        if (ck + 1 < 8) {
            const int k0 = (ck + 1) * 32, bn = (ck + 1) & 1;
#pragma unroll
            for (int it = 0; it < 2; it++) {
                int cw = it * THREADS + t;
                int hl = cw >> 8, idx = cw & 255, r = idx >> 2, u = idx & 3;
                const __half* src = (hl ? g_wl : g_wh) + (row0 + r) * 256 + k0 + u * 8;
                cpa16(sb + QSW + (bn * 2 + hl) * 4096 + sw64(r, u), src);
            }
#pragma unroll
            for (int it = 0; it < 8; it++) {
                int cx = it * THREADS + t;
                int hl = cx >> 10, idx = cx & 1023, k = idx >> 5, u = idx & 31;
                const __half* src = (hl ? g_xl : g_xh) + ((size_t)(b * 256 + k0 + k)) * N_ + n0 + u * 8;
                cpa16(sb + QSX + (bn * 2 + hl) * 16384 + (k * 32 + (u ^ (k & 7))) * 16, src);
            }
            CP_COMMIT();
            CP_WAIT(1);
        } else {
            CP_WAIT(0);
        }
        __syncthreads();

        const uint32_t baseWh = sb + QSW + (buf * 2 + 0) * 4096;
        const uint32_t baseWl = sb + QSW + (buf * 2 + 1) * 4096;
        const uint32_t baseXh = sb + QSX + (buf * 2 + 0) * 16384;
        const uint32_t baseXl = sb + QSX + (buf * 2 + 1) * 16384;

#pragma unroll
        for (int kb = 0; kb < 2; kb++) {
            uint32_t ah[2][4], al[2][4];
            ldsm4(ah[0], a64(baseWh, mqw,      kb * 2, lane));
            ldsm4(ah[1], a64(baseWh, mqw + 16, kb * 2, lane));
            ldsm4(al[0], a64(baseWl, mqw,      kb * 2, lane));
            ldsm4(al[1], a64(baseWl, mqw + 16, kb * 2, lane));
#pragma unroll
            for (int nt = 0; nt < 4; nt++) {
                uint32_t bh[4], bl[4];
                ldsm4t(bh, bxt(baseXh, kb * 16, nw + nt * 16, lane));
                ldsm4t(bl, bxt(baseXl, kb * 16, nw + nt * 16, lane));
#pragma unroll
                for (int mb = 0; mb < 2; mb++) {
                    mma_f16(o[mb][nt * 2 + 0], ah[mb], bh[0], bh[1]);
                    mma_f16(o[mb][nt * 2 + 1], ah[mb], bh[2], bh[3]);
                    mma_f16(o[mb][nt * 2 + 0], ah[mb], bl[0], bl[1]);
                    mma_f16(o[mb][nt * 2 + 1], ah[mb], bl[2], bl[3]);
                    mma_f16(o[mb][nt * 2 + 0], al[mb], bh[0], bh[1]);
                    mma_f16(o[mb][nt * 2 + 1], al[mb], bh[2], bh[3]);
                }
            }
        }
    }

    if (row0 == 0) {
#pragma unroll
        for (int mb = 0; mb < 2; mb++)
#pragma unroll
            for (int hh = 0; hh < 2; hh++) {
                int rg = mqw + mb * 16 + g + hh * 8;
                const bool isq = (rg < 32);
                const int d = isq ? rg : rg - 32;
                const float bias = isq ? bq[rg] : bk[rg - 32];
                __half* dh = isq ? g_qh : g_kh;
                __half* dl = isq ? g_ql : g_kl;
#pragma unroll
                for (int nb = 0; nb < 8; nb++)
#pragma unroll
                    for (int c2 = 0; c2 < 2; c2++) {
                        float val = o[mb][nb][hh * 2 + c2] + bias;
                        int n = n0 + nw + nb * 8 + tig * 2 + c2;
                        __half h = __float2half_rn(val);
                        __half l = __float2half_rn(val - __half2float(h));
                        size_t off = ((size_t)b * N_ + n) * D_ + d;
                        dh[off] = h; dl[off] = l;
                    }
            }
    } else {
#pragma unroll
        for (int mb = 0; mb < 2; mb++)
#pragma unroll
            for (int hh = 0; hh < 2; hh++) {
                int c = row0 - 64 + mqw + mb * 16 + g + hh * 8;
                const float bias = bv[c];
#pragma unroll
                for (int nb = 0; nb < 8; nb++) {
                    float v0 = o[mb][nb][hh * 2 + 0] + bias;
                    float v1 = o[mb][nb][hh * 2 + 1] + bias;
                    int n = n0 + nw + nb * 8 + tig * 2;
                    *(uint32_t*)(g_v + ((size_t)b * C_ + c) * (size_t)N_ + n) = h2pack(v0, v1);
                }
            }
    }
}

// ---------------------------------------------------------------------------
// fp16 flash attention — R10 (491.6us) structure: pipelined PV one tile
// behind, interleaved with softmax exps; EXACT online max (3 barriers/tile).
// Sole change vs R10: warp-vote skip of the O/lacc rescale when no row max
// updated (alpha == 1.0 exactly -> bit-identical).
// ---------------------------------------------------------------------------
__global__ __launch_bounds__(THREADS, 2) void attn_kernel(
    const float* __restrict__ x, const float* __restrict__ gamma_p,
    float* __restrict__ out)
{
    extern __shared__ char smem[];
    const uint32_t sb = smem_u32(smem);
    const int t    = threadIdx.x;
    const int w    = t >> 5;
    const int lane = t & 31;
    const int g    = lane >> 2;
    const int tig  = lane & 3;
    const int b    = blockIdx.y;
    const int q0   = blockIdx.x * QTILE;
    const int qg   = w & 1;
    const int sl   = w >> 1;
    const int mq   = qg * 32;

    const __half* qhp = g_qh + (size_t)b * N_ * D_;
    const __half* qlp = g_ql + (size_t)b * N_ * D_;
    const __half* khp = g_kh + (size_t)b * N_ * D_;
    const __half* klp = g_kl + (size_t)b * N_ * D_;
    const __half* vp  = g_v  + (size_t)b * C_ * (size_t)N_;

    // prefetch tile 0: K group, then V group (separate commits)
#pragma unroll
    for (int it = 0; it < 2; it++) {
        int chunk = it * THREADS + t;
        int hl = chunk >> 8, idx = chunk & 255, row = idx >> 2, u = idx & 3;
        const __half* src = (hl ? klp : khp) + (size_t)row * D_ + u * 8;
        cpa16(sb + SM_K + hl * 4096 + sw64(row, u), src);
    }
    CP_COMMIT();
#pragma unroll
    for (int it = 0; it < 8; it++) {
        int chunk = it * THREADS + t;
        int row = chunk >> 3, u = chunk & 7;
        cpa16(sb + SM_V + sw128(row, u), vp + (size_t)row * N_ + u * 8);
    }
    CP_COMMIT();

    // Q tile (hi/lo) plain load
#pragma unroll
    for (int it = 0; it < 2; it++) {
        int chunk = it * THREADS + t;
        int hl = chunk >> 8, idx = chunk & 255, row = idx >> 2, u = idx & 3;
        const __half* src = (hl ? qlp : qhp) + (size_t)(q0 + row) * D_ + u * 8;
        *(uint4*)(smem + SM_Q + hl * 4096 + sw64(row, u)) = *(const uint4*)src;
    }
    __syncthreads();

    // Q fragments (static across tiles)
    uint32_t qhf[2][2][4], qlf[2][2][4];
#pragma unroll
    for (int mb = 0; mb < 2; mb++)
#pragma unroll
        for (int kb = 0; kb < 2; kb++) {
            ldsm4(qhf[mb][kb], a64(sb + SM_Q,        mq + mb * 16, kb * 2, lane));
            ldsm4(qlf[mb][kb], a64(sb + SM_Q + 4096, mq + mb * 16, kb * 2, lane));
        }

    float o[2][8][4];
#pragma unroll
    for (int mb = 0; mb < 2; mb++)
#pragma unroll
        for (int nb = 0; nb < 8; nb++)
#pragma unroll
            for (int r = 0; r < 4; r++) o[mb][nb][r] = 0.f;

    float lacc[2][2] = {{0.f, 0.f}, {0.f, 0.f}};
    float mold[2][2];

    // ======================= peeled tile 0 =======================
    {
        CP_WAIT(1);          // K(0) done (V(0) may be in flight)
        __syncthreads();
        // prefetch K(1)
#pragma unroll
        for (int it = 0; it < 2; it++) {
            int chunk = it * THREADS + t;
            int hl = chunk >> 8, idx = chunk & 255, row = idx >> 2, u = idx & 3;
            const __half* src = (hl ? klp : khp) + (size_t)(KTILE + row) * D_ + u * 8;
            cpa16(sb + SM_K + (2 + hl) * 4096 + sw64(row, u), src);
        }
        CP_COMMIT();

        // S(0)
        float s[2][2][4];
#pragma unroll
        for (int mb = 0; mb < 2; mb++)
#pragma unroll
            for (int nb = 0; nb < 2; nb++)
#pragma unroll
                for (int r = 0; r < 4; r++) s[mb][nb][r] = 0.f;
#pragma unroll
        for (int kb = 0; kb < 2; kb++) {
            uint32_t khf[4], klf[4];
            ldsm4(khf, b64(sb + SM_K + 0 * 4096, sl * 16, kb * 2, lane));
            ldsm4(klf, b64(sb + SM_K + 1 * 4096, sl * 16, kb * 2, lane));
#pragma unroll
            for (int mb = 0; mb < 2; mb++)
#pragma unroll
                for (int nb = 0; nb < 2; nb++) {
                    mma_f16(s[mb][nb], qhf[mb][kb], khf[nb * 2], khf[nb * 2 + 1]);
                    mma_f16(s[mb][nb], qhf[mb][kb], klf[nb * 2], klf[nb * 2 + 1]);
                    mma_f16(s[mb][nb], qlf[mb][kb], khf[nb * 2], khf[nb * 2 + 1]);
                }
        }
        // max
        float mloc[2][2];
#pragma unroll
        for (int mb = 0; mb < 2; mb++) {
            mloc[mb][0] = fmaxf(fmaxf(s[mb][0][0], s[mb][0][1]), fmaxf(s[mb][1][0], s[mb][1][1]));
            mloc[mb][1] = fmaxf(fmaxf(s[mb][0][2], s[mb][0][3]), fmaxf(s[mb][1][2], s[mb][1][3]));
        }
#pragma unroll
        for (int mb = 0; mb < 2; mb++)
#pragma unroll
            for (int hf = 0; hf < 2; hf++) {
                float v = mloc[mb][hf];
                v = fmaxf(v, __shfl_xor_sync(0xffffffffu, v, 1));
                v = fmaxf(v, __shfl_xor_sync(0xffffffffu, v, 2));
                mloc[mb][hf] = v;
            }
        if (tig == 0) {
#pragma unroll
            for (int mb = 0; mb < 2; mb++)
#pragma unroll
                for (int hf = 0; hf < 2; hf++)
                    *(float*)(smem + SM_PM + (mq + mb * 16 + g + hf * 8) * 16 + sl * 4) = mloc[mb][hf];
        }
        __syncthreads();
#pragma unroll
        for (int mb = 0; mb < 2; mb++)
#pragma unroll
            for (int hf = 0; hf < 2; hf++) {
                int row = mq + mb * 16 + g + hf * 8;
                float4 pm = *(const float4*)(smem + SM_PM + row * 16);
                mold[mb][hf] = fmaxf(fmaxf(pm.x, pm.y), fmaxf(pm.z, pm.w));
            }
        // softmax(0) -> P buf 0
#pragma unroll
        for (int mb = 0; mb < 2; mb++)
#pragma unroll
            for (int nb = 0; nb < 2; nb++) {
                float e0 = __expf(s[mb][nb][0] - mold[mb][0]);
                float e1 = __expf(s[mb][nb][1] - mold[mb][0]);
                float e2 = __expf(s[mb][nb][2] - mold[mb][1]);
                float e3 = __expf(s[mb][nb][3] - mold[mb][1]);
                __half2 h01 = __floats2half2_rn(e0, e1);
                __half2 h23 = __floats2half2_rn(e2, e3);
                float2 f01 = __half22float2(h01), f23 = __half22float2(h23);
                lacc[mb][0] += f01.x + f01.y;
                lacc[mb][1] += f23.x + f23.y;
                int r0 = mq + mb * 16 + g;
                int u  = sl * 2 + nb;
                *(uint32_t*)(smem + SM_P + sw128(r0,     u) + tig * 4) = *(uint32_t*)&h01;
                *(uint32_t*)(smem + SM_P + sw128(r0 + 8, u) + tig * 4) = *(uint32_t*)&h23;
            }
        __syncthreads();   // P(0) visible
        // prefetch V(1)
#pragma unroll
        for (int it = 0; it < 8; it++) {
            int chunk = it * THREADS + t;
            int row = chunk >> 3, u = chunk & 7;
            cpa16(sb + SM_V + 32768 + sw128(row, u), vp + (size_t)row * N_ + KTILE + u * 8);
        }
        CP_COMMIT();
    }

    // ======================= main loop t=1..63 =======================
    for (int tile = 1; tile < NTILES; tile++) {
        const int buf = tile & 1;   // K/V/P write buffer; read side uses buf^1
        CP_WAIT(1);                 // K(t) + V(t-1) ready (V(t) may be in flight)
        __syncthreads();

        if (tile + 1 < NTILES) {
            const int jn = (tile + 1) * KTILE, bn = (tile + 1) & 1;
#pragma unroll
            for (int it = 0; it < 2; it++) {
                int chunk = it * THREADS + t;
                int hl = chunk >> 8, idx = chunk & 255, row = idx >> 2, u = idx & 3;
                const __half* src = (hl ? klp : khp) + (size_t)(jn + row) * D_ + u * 8;
                cpa16(sb + SM_K + (bn * 2 + hl) * 4096 + sw64(row, u), src);
            }
        }
        CP_COMMIT();   // K group committed every iteration (possibly empty) to keep order

        // ---- S(t) = Q K^T ----
        float s[2][2][4];
#pragma unroll
        for (int mb = 0; mb < 2; mb++)
#pragma unroll
            for (int nb = 0; nb < 2; nb++)
#pragma unroll
                for (int r = 0; r < 4; r++) s[mb][nb][r] = 0.f;
#pragma unroll
        for (int kb = 0; kb < 2; kb++) {
            uint32_t khf[4], klf[4];
            ldsm4(khf, b64(sb + SM_K + (buf * 2 + 0) * 4096, sl * 16, kb * 2, lane));
            ldsm4(klf, b64(sb + SM_K + (buf * 2 + 1) * 4096, sl * 16, kb * 2, lane));
#pragma unroll
            for (int mb = 0; mb < 2; mb++)
#pragma unroll
                for (int nb = 0; nb < 2; nb++) {
                    mma_f16(s[mb][nb], qhf[mb][kb], khf[nb * 2], khf[nb * 2 + 1]);
                    mma_f16(s[mb][nb], qhf[mb][kb], klf[nb * 2], klf[nb * 2 + 1]);
                    mma_f16(s[mb][nb], qlf[mb][kb], khf[nb * 2], khf[nb * 2 + 1]);
                }
        }

        // ---- row max exchange ----
        float mloc[2][2];
#pragma unroll
        for (int mb = 0; mb < 2; mb++) {
            mloc[mb][0] = fmaxf(fmaxf(s[mb][0][0], s[mb][0][1]), fmaxf(s[mb][1][0], s[mb][1][1]));
            mloc[mb][1] = fmaxf(fmaxf(s[mb][0][2], s[mb][0][3]), fmaxf(s[mb][1][2], s[mb][1][3]));
        }
#pragma unroll
        for (int mb = 0; mb < 2; mb++)
#pragma unroll
            for (int hf = 0; hf < 2; hf++) {
                float v = mloc[mb][hf];
                v = fmaxf(v, __shfl_xor_sync(0xffffffffu, v, 1));
                v = fmaxf(v, __shfl_xor_sync(0xffffffffu, v, 2));
                mloc[mb][hf] = v;
            }
        if (tig == 0) {
#pragma unroll
            for (int mb = 0; mb < 2; mb++)
#pragma unroll
                for (int hf = 0; hf < 2; hf++)
                    *(float*)(smem + SM_PM + (mq + mb * 16 + g + hf * 8) * 16 + sl * 4) = mloc[mb][hf];
        }
        __syncthreads();

        // ---- alpha(t) + warp-vote rescale skip (bit-exact: alpha==1 when no update)
        float al[2][2];
        bool upd = false;
#pragma unroll
        for (int mb = 0; mb < 2; mb++)
#pragma unroll
            for (int hf = 0; hf < 2; hf++) {
                int row = mq + mb * 16 + g + hf * 8;
                float4 pm = *(const float4*)(smem + SM_PM + row * 16);
                float mt = fmaxf(fmaxf(pm.x, pm.y), fmaxf(pm.z, pm.w));
                float mn = fmaxf(mold[mb][hf], mt);
                al[mb][hf] = __expf(mold[mb][hf] - mn);
                upd |= (mn > mold[mb][hf]);
                mold[mb][hf] = mn;
            }
        const bool do_scale = __any_sync(0xffffffffu, upd);

        // ---- interleaved: PV(t-1) MMAs + softmax(t) exps (independent pipes)
        float lsum[2][2] = {{0.f, 0.f}, {0.f, 0.f}};
        const uint32_t pR = sb + SM_P + (buf ^ 1) * 8192;
        const uint32_t vR = sb + SM_V + (buf ^ 1) * 32768;
        const int pWo = SM_P + buf * 8192;
#pragma unroll
        for (int kb = 0; kb < 4; kb++) {
            uint32_t phf[2][4];
            ldsm4(phf[0], a128(pR, mq,      kb * 2, lane));
            ldsm4(phf[1], a128(pR, mq + 16, kb * 2, lane));
#pragma unroll
            for (int nb2 = 0; nb2 < 4; nb2++) {
                uint32_t vhf[4];
                ldsm4(vhf, b128(vR, sl * 64 + nb2 * 16, kb * 2, lane));
                mma_f16(o[0][nb2 * 2 + 0], phf[0], vhf[0], vhf[1]);
                mma_f16(o[0][nb2 * 2 + 1], phf[0], vhf[2], vhf[3]);
                mma_f16(o[1][nb2 * 2 + 0], phf[1], vhf[0], vhf[1]);
                mma_f16(o[1][nb2 * 2 + 1], phf[1], vhf[2], vhf[3]);
            }
            // softmax chunk (mb,nb) = (kb>>1, kb&1)
            {
                const int mb = kb >> 1, nb = kb & 1;
                float e0 = __expf(s[mb][nb][0] - mold[mb][0]);
                float e1 = __expf(s[mb][nb][1] - mold[mb][0]);
                float e2 = __expf(s[mb][nb][2] - mold[mb][1]);
                float e3 = __expf(s[mb][nb][3] - mold[mb][1]);
                __half2 h01 = __floats2half2_rn(e0, e1);
                __half2 h23 = __floats2half2_rn(e2, e3);
                float2 f01 = __half22float2(h01), f23 = __half22float2(h23);
                lsum[mb][0] += f01.x + f01.y;
                lsum[mb][1] += f23.x + f23.y;
                int r0 = mq + mb * 16 + g;
                int u  = sl * 2 + nb;
                *(uint32_t*)(smem + pWo + sw128(r0,     u) + tig * 4) = *(uint32_t*)&h01;
                *(uint32_t*)(smem + pWo + sw128(r0 + 8, u) + tig * 4) = *(uint32_t*)&h23;
            }
        }
        // rescale to frame m(t): O = (O + PV(t-1)) * alpha — skipped when alpha==1
        if (do_scale) {
#pragma unroll
            for (int mb = 0; mb < 2; mb++)
#pragma unroll
                for (int nb = 0; nb < 8; nb++) {
                    o[mb][nb][0] *= al[mb][0]; o[mb][nb][1] *= al[mb][0];
                    o[mb][nb][2] *= al[mb][1]; o[mb][nb][3] *= al[mb][1];
                }
#pragma unroll
            for (int mb = 0; mb < 2; mb++)
#pragma unroll
                for (int hf = 0; hf < 2; hf++)
                    lacc[mb][hf] = lacc[mb][hf] * al[mb][hf] + lsum[mb][hf];
        } else {
#pragma unroll
            for (int mb = 0; mb < 2; mb++)
#pragma unroll
                for (int hf = 0; hf < 2; hf++)
                    lacc[mb][hf] += lsum[mb][hf];
        }

        __syncthreads();   // PV(t-1) done (V(t-1) free), P(t) visible

        if (tile + 1 < NTILES) {
            const int jn = (tile + 1) * KTILE, bn = (tile + 1) & 1;
#pragma unroll
            for (int it = 0; it < 8; it++) {
                int chunk = it * THREADS + t;
                int row = chunk >> 3, u = chunk & 7;
                cpa16(sb + SM_V + bn * 32768 + sw128(row, u), vp + (size_t)row * N_ + jn + u * 8);
            }
        }
        CP_COMMIT();   // V group committed every iteration (possibly empty)
    }

    // ======================= drain PV(63) =======================
    CP_WAIT(0);
    __syncthreads();
    {
        const int buf = (NTILES - 1) & 1;   // = 1
        const uint32_t pR = sb + SM_P + buf * 8192;
        const uint32_t vR = sb + SM_V + buf * 32768;
#pragma unroll
        for (int kb = 0; kb < 4; kb++) {
            uint32_t phf[2][4];
            ldsm4(phf[0], a128(pR, mq,      kb * 2, lane));
            ldsm4(phf[1], a128(pR, mq + 16, kb * 2, lane));
#pragma unroll
            for (int nb2 = 0; nb2 < 4; nb2++) {
                uint32_t vhf[4];
                ldsm4(vhf, b128(vR, sl * 64 + nb2 * 16, kb * 2, lane));
                mma_f16(o[0][nb2 * 2 + 0], phf[0], vhf[0], vhf[1]);
                mma_f16(o[0][nb2 * 2 + 1], phf[0], vhf[2], vhf[3]);
                mma_f16(o[1][nb2 * 2 + 0], phf[1], vhf[0], vhf[1]);
                mma_f16(o[1][nb2 * 2 + 1], phf[1], vhf[2], vhf[3]);
            }
        }
    }

    // ---- l reduction: quad shuffle, then cross-warp via smem ----
#pragma unroll
    for (int mb = 0; mb < 2; mb++)
#pragma unroll
        for (int hf = 0; hf < 2; hf++) {
            float v = lacc[mb][hf];
            v += __shfl_xor_sync(0xffffffffu, v, 1);
            v += __shfl_xor_sync(0xffffffffu, v, 2);
            lacc[mb][hf] = v;
        }
    if (tig == 0) {
#pragma unroll
        for (int mb = 0; mb < 2; mb++)
#pragma unroll
            for (int hf = 0; hf < 2; hf++) {
                int row = mq + mb * 16 + g + hf * 8;
                *(float*)(smem + SM_LS + (row * 4 + sl) * 4) = lacc[mb][hf];
            }
    }
    __syncthreads();
    if (t < 64) {
        const float* ls = (const float*)(smem + SM_LS) + t * 4;
        *(float*)(smem + SM_LR + t * 4) = 1.f / (ls[0] + ls[1] + ls[2] + ls[3]);
    }
    __syncthreads();

    // ---- epilogue: out = gamma * O / l + x ----
    {
        const float gma = *gamma_p;
#pragma unroll
        for (int mb = 0; mb < 2; mb++) {
            int r0 = mq + mb * 16 + g;
            int r1 = r0 + 8;
            float li0 = *(const float*)(smem + SM_LR + r0 * 4);
            float li1 = *(const float*)(smem + SM_LR + r1 * 4);
            int i0 = q0 + r0, i1 = q0 + r1;
#pragma unroll
            for (int nb = 0; nb < 8; nb++) {
                int c = sl * 64 + nb * 8 + tig * 2;
                size_t base0 = ((size_t)b * C_ + c) * (size_t)N_;
                size_t base1 = base0 + N_;
                out[base0 + i0] = gma * (o[mb][nb][0] * li0) + x[base0 + i0];
                out[base1 + i0] = gma * (o[mb][nb][1] * li0) + x[base1 + i0];
                out[base0 + i1] = gma * (o[mb][nb][2] * li1) + x[base0 + i1];
                out[base1 + i1] = gma * (o[mb][nb][3] * li1) + x[base1 + i1];
            }
        }
    }
}

extern "C" void kernel_launch(void* const* d_in, const int* in_sizes, int n_in,
                              void* d_out, int out_size) {
    const float* x  = (const float*)d_in[0];
    const float* Wq = (const float*)d_in[1];
    const float* bq = (const float*)d_in[2];
    const float* Wk = (const float*)d_in[3];
    const float* bk = (const float*)d_in[4];
    const float* Wv = (const float*)d_in[5];
    const float* bv = (const float*)d_in[6];
    const float* gm = (const float*)d_in[7];
    float* out = (float*)d_out;

    cudaFuncSetAttribute(qkv_mma, cudaFuncAttributeMaxDynamicSharedMemorySize, QS_TOTAL);
    cudaFuncSetAttribute(attn_kernel, cudaFuncAttributeMaxDynamicSharedMemorySize, SM_TOTAL);

    split_kernel<<<4136, 256>>>(x, Wq, Wk, Wv);
    qkv_mma<<<dim3(16, 5, 8), 256, QS_TOTAL>>>(bq, bk, bv);
    attn_kernel<<<dim3(N_ / QTILE, B_), THREADS, SM_TOTAL>>>(x, gm, out);
}

// round 14
// speedup vs baseline: 1.0375x; 1.0375x over previous
#include <cuda_runtime.h>
#include <cuda_fp16.h>
#include <cstdint>

#define B_ 8
#define C_ 256
#define D_ 32
#define N_ 4096
#define QTILE 64
#define KTILE 64
#define NTILES (N_ / KTILE)
#define THREADS 256

// attn smem byte offsets
#define SM_Q  0                         // Q hi/lo: 2 x 64 x 64B (SW64) = 8192
#define SM_K  8192                      // K[buf][hl]: 4 x 4096 (SW64)  = 16384
#define SM_V  24576                     // V[buf]: 2 x 32768 (SW128)    = 65536
#define SM_P  90112                     // P[buf]: 2 x 8192 (SW128)     = 16384
#define SM_PM 106496                    // pmax[64][4] floats           = 1024
#define SM_LS 107520                    // lsum[64][4] floats           = 1024
#define SM_LR 108544                    // lrecip[64] floats            = 256
#define SM_TOTAL 108800

// qkv_mma smem: W [buf2][hl2][4KB] + X [buf2][hl2][16KB]
#define QSW 0
#define QSX 16384
#define QS_TOTAL 81920

// ---------------------------------------------------------------------------
// scratch (allocation-free rule: device globals)
// ---------------------------------------------------------------------------
__device__ __half g_qh[(size_t)B_ * N_ * D_];
__device__ __half g_ql[(size_t)B_ * N_ * D_];
__device__ __half g_kh[(size_t)B_ * N_ * D_];
__device__ __half g_kl[(size_t)B_ * N_ * D_];
__device__ __half g_v [(size_t)B_ * C_ * N_];
__device__ __half g_xh[(size_t)B_ * C_ * N_];   // x split hi [b][c][n]
__device__ __half g_xl[(size_t)B_ * C_ * N_];   // x split lo
__device__ __half g_wh[320 * 256];              // [Wq;Wk;Wv] split hi
__device__ __half g_wl[320 * 256];

__device__ __forceinline__ uint32_t smem_u32(const void* p) {
    uint32_t a;
    asm("{ .reg .u64 t; cvta.to.shared.u64 t, %1; cvt.u32.u64 %0, t; }" : "=r"(a) : "l"(p));
    return a;
}
__device__ __forceinline__ void ldsm4(uint32_t* r, uint32_t addr) {
    asm volatile("ldmatrix.sync.aligned.m8n8.x4.shared.b16 {%0,%1,%2,%3}, [%4];"
                 : "=r"(r[0]), "=r"(r[1]), "=r"(r[2]), "=r"(r[3]) : "r"(addr));
}
__device__ __forceinline__ void ldsm4t(uint32_t* r, uint32_t addr) {
    asm volatile("ldmatrix.sync.aligned.m8n8.x4.trans.shared.b16 {%0,%1,%2,%3}, [%4];"
                 : "=r"(r[0]), "=r"(r[1]), "=r"(r[2]), "=r"(r[3]) : "r"(addr));
}
__device__ __forceinline__ void mma_f16(float* c, const uint32_t* a, uint32_t b0, uint32_t b1) {
    asm volatile("mma.sync.aligned.m16n8k16.row.col.f32.f16.f16.f32 "
                 "{%0,%1,%2,%3}, {%4,%5,%6,%7}, {%8,%9}, {%0,%1,%2,%3};"
                 : "+f"(c[0]), "+f"(c[1]), "+f"(c[2]), "+f"(c[3])
                 : "r"(a[0]), "r"(a[1]), "r"(a[2]), "r"(a[3]), "r"(b0), "r"(b1));
}
__device__ __forceinline__ void cpa16(uint32_t dst, const void* src) {
    asm volatile("cp.async.cg.shared.global [%0], [%1], 16;" :: "r"(dst), "l"(src));
}
#define CP_COMMIT() asm volatile("cp.async.commit_group;" ::: "memory")
#define CP_WAIT(n)  asm volatile("cp.async.wait_group %0;" :: "n"(n) : "memory")

// swizzles: 64B rows (Q/K/W) and 128B rows (V/P)
__device__ __forceinline__ uint32_t sw64(int row, int u)  { return row * 64  + ((u ^ ((row >> 1) & 3)) << 4); }
__device__ __forceinline__ uint32_t sw128(int row, int u) { return row * 128 + ((u ^ (row & 7)) << 4); }

// ldmatrix x4 address helpers
__device__ __forceinline__ uint32_t a64(uint32_t base, int row0, int k16, int lane) {
    int lr = lane & 7, grp = lane >> 3;
    return base + sw64(row0 + lr + (grp & 1) * 8, k16 + (grp >> 1));
}
__device__ __forceinline__ uint32_t b64(uint32_t base, int row0, int k16, int lane) {
    int lr = lane & 7, grp = lane >> 3;
    return base + sw64(row0 + lr + (grp >> 1) * 8, k16 + (grp & 1));
}
__device__ __forceinline__ uint32_t a128(uint32_t base, int row0, int k16, int lane) {
    int lr = lane & 7, grp = lane >> 3;
    return base + sw128(row0 + lr + (grp & 1) * 8, k16 + (grp >> 1));
}
__device__ __forceinline__ uint32_t b128(uint32_t base, int row0, int k16, int lane) {
    int lr = lane & 7, grp = lane >> 3;
    return base + sw128(row0 + lr + (grp >> 1) * 8, k16 + (grp & 1));
}
// B-fragment (trans) from X stored [k][n] (512B rows, k-XOR swizzle on 16B units)
__device__ __forceinline__ uint32_t bxt(uint32_t base, int k0, int n0, int lane) {
    int lr = lane & 7, grp = lane >> 3;
    int k  = k0 + lr + (grp & 1) * 8;
    int un = (n0 >> 3) + (grp >> 1);
    return base + (k * 32 + (un ^ (k & 7))) * 16;
}
__device__ __forceinline__ uint32_t h2pack(float a, float b) {
    __half2 h = __floats2half2_rn(a, b);
    return *reinterpret_cast<uint32_t*>(&h);
}

// ---------------------------------------------------------------------------
// split kernel: x -> g_xh/g_xl, [Wq;Wk;Wv] -> g_wh/g_wl (fp16 hi/lo)
// ---------------------------------------------------------------------------
__global__ __launch_bounds__(256) void split_kernel(
    const float* __restrict__ x,
    const float* __restrict__ Wq, const float* __restrict__ Wk,
    const float* __restrict__ Wv)
{
    const int bid = blockIdx.x;
    const int t   = threadIdx.x;
    if (bid < 4096) {
        size_t base = (size_t)bid * 2048 + (size_t)t * 8;
        float4 v0 = *(const float4*)(x + base);
        float4 v1 = *(const float4*)(x + base + 4);
        float vv[8] = {v0.x, v0.y, v0.z, v0.w, v1.x, v1.y, v1.z, v1.w};
        __half h[8], l[8];
#pragma unroll
        for (int i = 0; i < 8; i++) {
            h[i] = __float2half_rn(vv[i]);
            l[i] = __float2half_rn(vv[i] - __half2float(h[i]));
        }
        *(uint4*)(g_xh + base) = *(uint4*)h;
        *(uint4*)(g_xl + base) = *(uint4*)l;
    } else {
        int idx = (bid - 4096) * 2048 + t * 8;
        if (idx < 320 * 256) {
            int row = idx >> 8, col = idx & 255;
            const float* src;
            if (row < 32)       src = Wq + row * 256 + col;
            else if (row < 64)  src = Wk + (row - 32) * 256 + col;
            else                src = Wv + (row - 64) * 256 + col;
            float4 v0 = *(const float4*)(src);
            float4 v1 = *(const float4*)(src + 4);
            float vv[8] = {v0.x, v0.y, v0.z, v0.w, v1.x, v1.y, v1.z, v1.w};
            __half h[8], l[8];
#pragma unroll
            for (int i = 0; i < 8; i++) {
                h[i] = __float2half_rn(vv[i]);
                l[i] = __float2half_rn(vv[i] - __half2float(h[i]));
            }
            *(uint4*)(g_wh + idx) = *(uint4*)h;
            *(uint4*)(g_wl + idx) = *(uint4*)l;
        }
    }
}

// ---------------------------------------------------------------------------
// qkv via tensor cores: Y = W @ X + bias, 3-term fp16.
// ---------------------------------------------------------------------------
__global__ __launch_bounds__(256, 2) void qkv_mma(
    const float* __restrict__ bq, const float* __restrict__ bk,
    const float* __restrict__ bv)
{
    extern __shared__ char smem[];
    const uint32_t sb = smem_u32(smem);
    const int t    = threadIdx.x;
    const int w    = t >> 5;
    const int lane = t & 31;
    const int g    = lane >> 2;
    const int tig  = lane & 3;
    const int n0   = blockIdx.x * 256;
    const int row0 = blockIdx.y * 64;
    const int b    = blockIdx.z;
    const int mqw  = (w & 1) * 32;
    const int nw   = (w >> 1) * 64;

    {
        const int k0 = 0;
#pragma unroll
        for (int it = 0; it < 2; it++) {
            int cw = it * THREADS + t;
            int hl = cw >> 8, idx = cw & 255, r = idx >> 2, u = idx & 3;
            const __half* src = (hl ? g_wl : g_wh) + (row0 + r) * 256 + k0 + u * 8;
            cpa16(sb + QSW + hl * 4096 + sw64(r, u), src);
        }
#pragma unroll
        for (int it = 0; it < 8; it++) {
            int cx = it * THREADS + t;
            int hl = cx >> 10, idx = cx & 1023, k = idx >> 5, u = idx & 31;
            const __half* src = (hl ? g_xl : g_xh) + ((size_t)(b * 256 + k0 + k)) * N_ + n0 + u * 8;
            cpa16(sb + QSX + hl * 16384 + (k * 32 + (u ^ (k & 7))) * 16, src);
        }
        CP_COMMIT();
    }

    float o[2][8][4];
#pragma unroll
    for (int mb = 0; mb < 2; mb++)
#pragma unroll
        for (int nb = 0; nb < 8; nb++)
#pragma unroll
            for (int r = 0; r < 4; r++) o[mb][nb][r] = 0.f;

    for (int ck = 0; ck < 8; ck++) {
        const int buf = ck & 1;
        __syncthreads();
        if (ck + 1 < 8) {
            const int k0 = (ck + 1) * 32, bn = (ck + 1) & 1;
#pragma unroll
            for (int it = 0; it < 2; it++) {
                int cw = it * THREADS + t;
                int hl = cw >> 8, idx = cw & 255, r = idx >> 2, u = idx & 3;
                const __half* src = (hl ? g_wl : g_wh) + (row0 + r) * 256 + k0 + u * 8;
                cpa16(sb + QSW + (bn * 2 + hl) * 4096 + sw64(r, u), src);
            }
#pragma unroll
            for (int it = 0; it < 8; it++) {
                int cx = it * THREADS + t;
                int hl = cx >> 10, idx = cx & 1023, k = idx >> 5, u = idx & 31;
                const __half* src = (hl ? g_xl : g_xh) + ((size_t)(b * 256 + k0 + k)) * N_ + n0 + u * 8;
                cpa16(sb + QSX + (bn * 2 + hl) * 16384 + (k * 32 + (u ^ (k & 7))) * 16, src);
            }
            CP_COMMIT();
            CP_WAIT(1);
        } else {
            CP_WAIT(0);
        }
        __syncthreads();

        const uint32_t baseWh = sb + QSW + (buf * 2 + 0) * 4096;
        const uint32_t baseWl = sb + QSW + (buf * 2 + 1) * 4096;
        const uint32_t baseXh = sb + QSX + (buf * 2 + 0) * 16384;
        const uint32_t baseXl = sb + QSX + (buf * 2 + 1) * 16384;

#pragma unroll
        for (int kb = 0; kb < 2; kb++) {
            uint32_t ah[2][4], al[2][4];
            ldsm4(ah[0], a64(baseWh, mqw,      kb * 2, lane));
            ldsm4(ah[1], a64(baseWh, mqw + 16, kb * 2, lane));
            ldsm4(al[0], a64(baseWl, mqw,      kb * 2, lane));
            ldsm4(al[1], a64(baseWl, mqw + 16, kb * 2, lane));
#pragma unroll
            for (int nt = 0; nt < 4; nt++) {
                uint32_t bh[4], bl[4];
                ldsm4t(bh, bxt(baseXh, kb * 16, nw + nt * 16, lane));
                ldsm4t(bl, bxt(baseXl, kb * 16, nw + nt * 16, lane));
#pragma unroll
                for (int mb = 0; mb < 2; mb++) {
                    mma_f16(o[mb][nt * 2 + 0], ah[mb], bh[0], bh[1]);
                    mma_f16(o[mb][nt * 2 + 1], ah[mb], bh[2], bh[3]);
                    mma_f16(o[mb][nt * 2 + 0], ah[mb], bl[0], bl[1]);
                    mma_f16(o[mb][nt * 2 + 1], ah[mb], bl[2], bl[3]);
                    mma_f16(o[mb][nt * 2 + 0], al[mb], bh[0], bh[1]);
                    mma_f16(o[mb][nt * 2 + 1], al[mb], bh[2], bh[3]);
                }
            }
        }
    }

    if (row0 == 0) {
#pragma unroll
        for (int mb = 0; mb < 2; mb++)
#pragma unroll
            for (int hh = 0; hh < 2; hh++) {
                int rg = mqw + mb * 16 + g + hh * 8;
                const bool isq = (rg < 32);
                const int d = isq ? rg : rg - 32;
                const float bias = isq ? bq[rg] : bk[rg - 32];
                __half* dh = isq ? g_qh : g_kh;
                __half* dl = isq ? g_ql : g_kl;
#pragma unroll
                for (int nb = 0; nb < 8; nb++)
#pragma unroll
                    for (int c2 = 0; c2 < 2; c2++) {
                        float val = o[mb][nb][hh * 2 + c2] + bias;
                        int n = n0 + nw + nb * 8 + tig * 2 + c2;
                        __half h = __float2half_rn(val);
                        __half l = __float2half_rn(val - __half2float(h));
                        size_t off = ((size_t)b * N_ + n) * D_ + d;
                        dh[off] = h; dl[off] = l;
                    }
            }
    } else {
#pragma unroll
        for (int mb = 0; mb < 2; mb++)
#pragma unroll
            for (int hh = 0; hh < 2; hh++) {
                int c = row0 - 64 + mqw + mb * 16 + g + hh * 8;
                const float bias = bv[c];
#pragma unroll
                for (int nb = 0; nb < 8; nb++) {
                    float v0 = o[mb][nb][hh * 2 + 0] + bias;
                    float v1 = o[mb][nb][hh * 2 + 1] + bias;
                    int n = n0 + nw + nb * 8 + tig * 2;
                    *(uint32_t*)(g_v + ((size_t)b * C_ + c) * (size_t)N_ + n) = h2pack(v0, v1);
                }
            }
    }
}

// ---------------------------------------------------------------------------
// fp16 flash attention — exact R10 (491.6us): PV pipelined one tile behind,
// interleaved with softmax exps; exact online max; unconditional rescale.
// 1 CTA per (batch, 64-q tile), 256 thr, 2 CTAs/SM.
// ---------------------------------------------------------------------------
__global__ __launch_bounds__(THREADS, 2) void attn_kernel(
    const float* __restrict__ x, const float* __restrict__ gamma_p,
    float* __restrict__ out)
{
    extern __shared__ char smem[];
    const uint32_t sb = smem_u32(smem);
    const int t    = threadIdx.x;
    const int w    = t >> 5;
    const int lane = t & 31;
    const int g    = lane >> 2;
    const int tig  = lane & 3;
    const int b    = blockIdx.y;
    const int q0   = blockIdx.x * QTILE;
    const int qg   = w & 1;
    const int sl   = w >> 1;
    const int mq   = qg * 32;

    const __half* qhp = g_qh + (size_t)b * N_ * D_;
    const __half* qlp = g_ql + (size_t)b * N_ * D_;
    const __half* khp = g_kh + (size_t)b * N_ * D_;
    const __half* klp = g_kl + (size_t)b * N_ * D_;
    const __half* vp  = g_v  + (size_t)b * C_ * (size_t)N_;

    // prefetch tile 0: K group, then V group (separate commits!)
#pragma unroll
    for (int it = 0; it < 2; it++) {
        int chunk = it * THREADS + t;
        int hl = chunk >> 8, idx = chunk & 255, row = idx >> 2, u = idx & 3;
        const __half* src = (hl ? klp : khp) + (size_t)row * D_ + u * 8;
        cpa16(sb + SM_K + hl * 4096 + sw64(row, u), src);
    }
    CP_COMMIT();
#pragma unroll
    for (int it = 0; it < 8; it++) {
        int chunk = it * THREADS + t;
        int row = chunk >> 3, u = chunk & 7;
        cpa16(sb + SM_V + sw128(row, u), vp + (size_t)row * N_ + u * 8);
    }
    CP_COMMIT();

    // Q tile (hi/lo) plain load
#pragma unroll
    for (int it = 0; it < 2; it++) {
        int chunk = it * THREADS + t;
        int hl = chunk >> 8, idx = chunk & 255, row = idx >> 2, u = idx & 3;
        const __half* src = (hl ? qlp : qhp) + (size_t)(q0 + row) * D_ + u * 8;
        *(uint4*)(smem + SM_Q + hl * 4096 + sw64(row, u)) = *(const uint4*)src;
    }
    __syncthreads();

    // Q fragments (static across tiles)
    uint32_t qhf[2][2][4], qlf[2][2][4];
#pragma unroll
    for (int mb = 0; mb < 2; mb++)
#pragma unroll
        for (int kb = 0; kb < 2; kb++) {
            ldsm4(qhf[mb][kb], a64(sb + SM_Q,        mq + mb * 16, kb * 2, lane));
            ldsm4(qlf[mb][kb], a64(sb + SM_Q + 4096, mq + mb * 16, kb * 2, lane));
        }

    float o[2][8][4];
#pragma unroll
    for (int mb = 0; mb < 2; mb++)
#pragma unroll
        for (int nb = 0; nb < 8; nb++)
#pragma unroll
            for (int r = 0; r < 4; r++) o[mb][nb][r] = 0.f;

    float lacc[2][2] = {{0.f, 0.f}, {0.f, 0.f}};
    float mold[2][2];

    // ======================= peeled tile 0 =======================
    {
        CP_WAIT(1);          // K(0) done (V(0) may be in flight)
        __syncthreads();
        // prefetch K(1)
#pragma unroll
        for (int it = 0; it < 2; it++) {
            int chunk = it * THREADS + t;
            int hl = chunk >> 8, idx = chunk & 255, row = idx >> 2, u = idx & 3;
            const __half* src = (hl ? klp : khp) + (size_t)(KTILE + row) * D_ + u * 8;
            cpa16(sb + SM_K + (2 + hl) * 4096 + sw64(row, u), src);
        }
        CP_COMMIT();

        // S(0)
        float s[2][2][4];
#pragma unroll
        for (int mb = 0; mb < 2; mb++)
#pragma unroll
            for (int nb = 0; nb < 2; nb++)
#pragma unroll
                for (int r = 0; r < 4; r++) s[mb][nb][r] = 0.f;
#pragma unroll
        for (int kb = 0; kb < 2; kb++) {
            uint32_t khf[4], klf[4];
            ldsm4(khf, b64(sb + SM_K + 0 * 4096, sl * 16, kb * 2, lane));
            ldsm4(klf, b64(sb + SM_K + 1 * 4096, sl * 16, kb * 2, lane));
#pragma unroll
            for (int mb = 0; mb < 2; mb++)
#pragma unroll
                for (int nb = 0; nb < 2; nb++) {
                    mma_f16(s[mb][nb], qhf[mb][kb], khf[nb * 2], khf[nb * 2 + 1]);
                    mma_f16(s[mb][nb], qhf[mb][kb], klf[nb * 2], klf[nb * 2 + 1]);
                    mma_f16(s[mb][nb], qlf[mb][kb], khf[nb * 2], khf[nb * 2 + 1]);
                }
        }
        // max
        float mloc[2][2];
#pragma unroll
        for (int mb = 0; mb < 2; mb++) {
            mloc[mb][0] = fmaxf(fmaxf(s[mb][0][0], s[mb][0][1]), fmaxf(s[mb][1][0], s[mb][1][1]));
            mloc[mb][1] = fmaxf(fmaxf(s[mb][0][2], s[mb][0][3]), fmaxf(s[mb][1][2], s[mb][1][3]));
        }
#pragma unroll
        for (int mb = 0; mb < 2; mb++)
#pragma unroll
            for (int hf = 0; hf < 2; hf++) {
                float v = mloc[mb][hf];
                v = fmaxf(v, __shfl_xor_sync(0xffffffffu, v, 1));
                v = fmaxf(v, __shfl_xor_sync(0xffffffffu, v, 2));
                mloc[mb][hf] = v;
            }
        if (tig == 0) {
#pragma unroll
            for (int mb = 0; mb < 2; mb++)
#pragma unroll
                for (int hf = 0; hf < 2; hf++)
                    *(float*)(smem + SM_PM + (mq + mb * 16 + g + hf * 8) * 16 + sl * 4) = mloc[mb][hf];
        }
        __syncthreads();
#pragma unroll
        for (int mb = 0; mb < 2; mb++)
#pragma unroll
            for (int hf = 0; hf < 2; hf++) {
                int row = mq + mb * 16 + g + hf * 8;
                float4 pm = *(const float4*)(smem + SM_PM + row * 16);
                mold[mb][hf] = fmaxf(fmaxf(pm.x, pm.y), fmaxf(pm.z, pm.w));
            }
        // softmax(0) -> P buf 0
#pragma unroll
        for (int mb = 0; mb < 2; mb++)
#pragma unroll
            for (int nb = 0; nb < 2; nb++) {
                float e0 = __expf(s[mb][nb][0] - mold[mb][0]);
                float e1 = __expf(s[mb][nb][1] - mold[mb][0]);
                float e2 = __expf(s[mb][nb][2] - mold[mb][1]);
                float e3 = __expf(s[mb][nb][3] - mold[mb][1]);
                __half2 h01 = __floats2half2_rn(e0, e1);
                __half2 h23 = __floats2half2_rn(e2, e3);
                float2 f01 = __half22float2(h01), f23 = __half22float2(h23);
                lacc[mb][0] += f01.x + f01.y;
                lacc[mb][1] += f23.x + f23.y;
                int r0 = mq + mb * 16 + g;
                int u  = sl * 2 + nb;
                *(uint32_t*)(smem + SM_P + sw128(r0,     u) + tig * 4) = *(uint32_t*)&h01;
                *(uint32_t*)(smem + SM_P + sw128(r0 + 8, u) + tig * 4) = *(uint32_t*)&h23;
            }
        __syncthreads();   // P(0) visible
        // prefetch V(1)
#pragma unroll
        for (int it = 0; it < 8; it++) {
            int chunk = it * THREADS + t;
            int row = chunk >> 3, u = chunk & 7;
            cpa16(sb + SM_V + 32768 + sw128(row, u), vp + (size_t)row * N_ + KTILE + u * 8);
        }
        CP_COMMIT();
    }

    // ======================= main loop t=1..63 =======================
    for (int tile = 1; tile < NTILES; tile++) {
        const int buf = tile & 1;   // K/V/P write buffer; read side uses buf^1
        CP_WAIT(1);                 // K(t) + V(t-1) ready (V(t) may be in flight)
        __syncthreads();

        if (tile + 1 < NTILES) {
            const int jn = (tile + 1) * KTILE, bn = (tile + 1) & 1;
#pragma unroll
            for (int it = 0; it < 2; it++) {
                int chunk = it * THREADS + t;
                int hl = chunk >> 8, idx = chunk & 255, row = idx >> 2, u = idx & 3;
                const __half* src = (hl ? klp : khp) + (size_t)(jn + row) * D_ + u * 8;
                cpa16(sb + SM_K + (bn * 2 + hl) * 4096 + sw64(row, u), src);
            }
        }
        CP_COMMIT();   // K group committed every iteration (possibly empty) to keep order

        // ---- S(t) = Q K^T ----
        float s[2][2][4];
#pragma unroll
        for (int mb = 0; mb < 2; mb++)
#pragma unroll
            for (int nb = 0; nb < 2; nb++)
#pragma unroll
                for (int r = 0; r < 4; r++) s[mb][nb][r] = 0.f;
#pragma unroll
        for (int kb = 0; kb < 2; kb++) {
            uint32_t khf[4], klf[4];
            ldsm4(khf, b64(sb + SM_K + (buf * 2 + 0) * 4096, sl * 16, kb * 2, lane));
            ldsm4(klf, b64(sb + SM_K + (buf * 2 + 1) * 4096, sl * 16, kb * 2, lane));
#pragma unroll
            for (int mb = 0; mb < 2; mb++)
#pragma unroll
                for (int nb = 0; nb < 2; nb++) {
                    mma_f16(s[mb][nb], qhf[mb][kb], khf[nb * 2], khf[nb * 2 + 1]);
                    mma_f16(s[mb][nb], qhf[mb][kb], klf[nb * 2], klf[nb * 2 + 1]);
                    mma_f16(s[mb][nb], qlf[mb][kb], khf[nb * 2], khf[nb * 2 + 1]);
                }
        }

        // ---- row max exchange ----
        float mloc[2][2];
#pragma unroll
        for (int mb = 0; mb < 2; mb++) {
            mloc[mb][0] = fmaxf(fmaxf(s[mb][0][0], s[mb][0][1]), fmaxf(s[mb][1][0], s[mb][1][1]));
            mloc[mb][1] = fmaxf(fmaxf(s[mb][0][2], s[mb][0][3]), fmaxf(s[mb][1][2], s[mb][1][3]));
        }
#pragma unroll
        for (int mb = 0; mb < 2; mb++)
#pragma unroll
            for (int hf = 0; hf < 2; hf++) {
                float v = mloc[mb][hf];
                v = fmaxf(v, __shfl_xor_sync(0xffffffffu, v, 1));
                v = fmaxf(v, __shfl_xor_sync(0xffffffffu, v, 2));
                mloc[mb][hf] = v;
            }
        if (tig == 0) {
#pragma unroll
            for (int mb = 0; mb < 2; mb++)
#pragma unroll
                for (int hf = 0; hf < 2; hf++)
                    *(float*)(smem + SM_PM + (mq + mb * 16 + g + hf * 8) * 16 + sl * 4) = mloc[mb][hf];
        }
        __syncthreads();

        // ---- alpha(t) ----
        float al[2][2];
#pragma unroll
        for (int mb = 0; mb < 2; mb++)
#pragma unroll
            for (int hf = 0; hf < 2; hf++) {
                int row = mq + mb * 16 + g + hf * 8;
                float4 pm = *(const float4*)(smem + SM_PM + row * 16);
                float mt = fmaxf(fmaxf(pm.x, pm.y), fmaxf(pm.z, pm.w));
                float mn = fmaxf(mold[mb][hf], mt);
                al[mb][hf] = __expf(mold[mb][hf] - mn);
                mold[mb][hf] = mn;
            }

        // ---- interleaved: PV(t-1) MMAs + softmax(t) exps (independent pipes)
        float lsum[2][2] = {{0.f, 0.f}, {0.f, 0.f}};
        const uint32_t pR = sb + SM_P + (buf ^ 1) * 8192;
        const uint32_t vR = sb + SM_V + (buf ^ 1) * 32768;
        const int pWo = SM_P + buf * 8192;
#pragma unroll
        for (int kb = 0; kb < 4; kb++) {
            uint32_t phf[2][4];
            ldsm4(phf[0], a128(pR, mq,      kb * 2, lane));
            ldsm4(phf[1], a128(pR, mq + 16, kb * 2, lane));
#pragma unroll
            for (int nb2 = 0; nb2 < 4; nb2++) {
                uint32_t vhf[4];
                ldsm4(vhf, b128(vR, sl * 64 + nb2 * 16, kb * 2, lane));
                mma_f16(o[0][nb2 * 2 + 0], phf[0], vhf[0], vhf[1]);
                mma_f16(o[0][nb2 * 2 + 1], phf[0], vhf[2], vhf[3]);
                mma_f16(o[1][nb2 * 2 + 0], phf[1], vhf[0], vhf[1]);
                mma_f16(o[1][nb2 * 2 + 1], phf[1], vhf[2], vhf[3]);
            }
            // softmax chunk (mb,nb) = (kb>>1, kb&1)
            {
                const int mb = kb >> 1, nb = kb & 1;
                float e0 = __expf(s[mb][nb][0] - mold[mb][0]);
                float e1 = __expf(s[mb][nb][1] - mold[mb][0]);
                float e2 = __expf(s[mb][nb][2] - mold[mb][1]);
                float e3 = __expf(s[mb][nb][3] - mold[mb][1]);
                __half2 h01 = __floats2half2_rn(e0, e1);
                __half2 h23 = __floats2half2_rn(e2, e3);
                float2 f01 = __half22float2(h01), f23 = __half22float2(h23);
                lsum[mb][0] += f01.x + f01.y;
                lsum[mb][1] += f23.x + f23.y;
                int r0 = mq + mb * 16 + g;
                int u  = sl * 2 + nb;
                *(uint32_t*)(smem + pWo + sw128(r0,     u) + tig * 4) = *(uint32_t*)&h01;
                *(uint32_t*)(smem + pWo + sw128(r0 + 8, u) + tig * 4) = *(uint32_t*)&h23;
            }
        }
        // rescale to frame m(t): O = (O + PV(t-1)) * alpha
#pragma unroll
        for (int mb = 0; mb < 2; mb++)
#pragma unroll
            for (int nb = 0; nb < 8; nb++) {
                o[mb][nb][0] *= al[mb][0]; o[mb][nb][1] *= al[mb][0];
                o[mb][nb][2] *= al[mb][1]; o[mb][nb][3] *= al[mb][1];
            }
#pragma unroll
        for (int mb = 0; mb < 2; mb++)
#pragma unroll
            for (int hf = 0; hf < 2; hf++)
                lacc[mb][hf] = lacc[mb][hf] * al[mb][hf] + lsum[mb][hf];

        __syncthreads();   // PV(t-1) done (V(t-1) free), P(t) visible

        if (tile + 1 < NTILES) {
            const int jn = (tile + 1) * KTILE, bn = (tile + 1) & 1;
#pragma unroll
            for (int it = 0; it < 8; it++) {
                int chunk = it * THREADS + t;
                int row = chunk >> 3, u = chunk & 7;
                cpa16(sb + SM_V + bn * 32768 + sw128(row, u), vp + (size_t)row * N_ + jn + u * 8);
            }
        }
        CP_COMMIT();   // V group committed every iteration (possibly empty)
    }

    // ======================= drain PV(63) =======================
    CP_WAIT(0);
    __syncthreads();
    {
        const int buf = (NTILES - 1) & 1;   // = 1
        const uint32_t pR = sb + SM_P + buf * 8192;
        const uint32_t vR = sb + SM_V + buf * 32768;
#pragma unroll
        for (int kb = 0; kb < 4; kb++) {
            uint32_t phf[2][4];
            ldsm4(phf[0], a128(pR, mq,      kb * 2, lane));
            ldsm4(phf[1], a128(pR, mq + 16, kb * 2, lane));
#pragma unroll
            for (int nb2 = 0; nb2 < 4; nb2++) {
                uint32_t vhf[4];
                ldsm4(vhf, b128(vR, sl * 64 + nb2 * 16, kb * 2, lane));
                mma_f16(o[0][nb2 * 2 + 0], phf[0], vhf[0], vhf[1]);
                mma_f16(o[0][nb2 * 2 + 1], phf[0], vhf[2], vhf[3]);
                mma_f16(o[1][nb2 * 2 + 0], phf[1], vhf[0], vhf[1]);
                mma_f16(o[1][nb2 * 2 + 1], phf[1], vhf[2], vhf[3]);
            }
        }
    }

    // ---- l reduction: quad shuffle, then cross-warp via smem ----
#pragma unroll
    for (int mb = 0; mb < 2; mb++)
#pragma unroll
        for (int hf = 0; hf < 2; hf++) {
            float v = lacc[mb][hf];
            v += __shfl_xor_sync(0xffffffffu, v, 1);
            v += __shfl_xor_sync(0xffffffffu, v, 2);
            lacc[mb][hf] = v;
        }
    if (tig == 0) {
#pragma unroll
        for (int mb = 0; mb < 2; mb++)
#pragma unroll
            for (int hf = 0; hf < 2; hf++) {
                int row = mq + mb * 16 + g + hf * 8;
                *(float*)(smem + SM_LS + (row * 4 + sl) * 4) = lacc[mb][hf];
            }
    }
    __syncthreads();
    if (t < 64) {
        const float* ls = (const float*)(smem + SM_LS) + t * 4;
        *(float*)(smem + SM_LR + t * 4) = 1.f / (ls[0] + ls[1] + ls[2] + ls[3]);
    }
    __syncthreads();

    // ---- epilogue: out = gamma * O / l + x ----
    {
        const float gma = *gamma_p;
#pragma unroll
        for (int mb = 0; mb < 2; mb++) {
            int r0 = mq + mb * 16 + g;
            int r1 = r0 + 8;
            float li0 = *(const float*)(smem + SM_LR + r0 * 4);
            float li1 = *(const float*)(smem + SM_LR + r1 * 4);
            int i0 = q0 + r0, i1 = q0 + r1;
#pragma unroll
            for (int nb = 0; nb < 8; nb++) {
                int c = sl * 64 + nb * 8 + tig * 2;
                size_t base0 = ((size_t)b * C_ + c) * (size_t)N_;
                size_t base1 = base0 + N_;
                out[base0 + i0] = gma * (o[mb][nb][0] * li0) + x[base0 + i0];
                out[base1 + i0] = gma * (o[mb][nb][1] * li0) + x[base1 + i0];
                out[base0 + i1] = gma * (o[mb][nb][2] * li1) + x[base0 + i1];
                out[base1 + i1] = gma * (o[mb][nb][3] * li1) + x[base1 + i1];
            }
        }
    }
}

extern "C" void kernel_launch(void* const* d_in, const int* in_sizes, int n_in,
                              void* d_out, int out_size) {
    const float* x  = (const float*)d_in[0];
    const float* Wq = (const float*)d_in[1];
    const float* bq = (const float*)d_in[2];
    const float* Wk = (const float*)d_in[3];
    const float* bk = (const float*)d_in[4];
    const float* Wv = (const float*)d_in[5];
    const float* bv = (const float*)d_in[6];
    const float* gm = (const float*)d_in[7];
    float* out = (float*)d_out;

    cudaFuncSetAttribute(qkv_mma, cudaFuncAttributeMaxDynamicSharedMemorySize, QS_TOTAL);
    cudaFuncSetAttribute(attn_kernel, cudaFuncAttributeMaxDynamicSharedMemorySize, SM_TOTAL);

    split_kernel<<<4136, 256>>>(x, Wq, Wk, Wv);
    qkv_mma<<<dim3(16, 5, 8), 256, QS_TOTAL>>>(bq, bk, bv);
    attn_kernel<<<dim3(N_ / QTILE, B_), THREADS, SM_TOTAL>>>(x, gm, out);
}

// round 15
// speedup vs baseline: 1.1804x; 1.1377x over previous
#include <cuda_runtime.h>
#include <cuda_fp16.h>
#include <cstdint>

#define B_ 8
#define C_ 256
#define D_ 32
#define N_ 4096
#define QTILE 64
#define KTILE 64
#define NTILES (N_ / KTILE)
#define THREADS 256
#define LOG2E 1.4426950408889634f

// attn smem byte offsets
#define SM_Q  0                         // Q hi/lo: 2 x 64 x 64B (SW64) = 8192
#define SM_K  8192                      // K[buf][hl]: 4 x 4096 (SW64)  = 16384
#define SM_V  24576                     // V[buf]: 2 x 32768 (SW128)    = 65536
#define SM_P  90112                     // P[buf]: 2 x 8192 (SW128)     = 16384
#define SM_PM 106496                    // pmax[64][4] floats           = 1024
#define SM_LS 107520                    // lsum[64][4] floats           = 1024
#define SM_LR 108544                    // lrecip[64] floats            = 256
#define SM_TOTAL 108800

// qkv_mma smem: W [buf2][hl2][4KB] + X [buf2][hl2][16KB]
#define QSW 0
#define QSX 16384
#define QS_TOTAL 81920

// ---------------------------------------------------------------------------
// scratch (allocation-free rule: device globals)
// ---------------------------------------------------------------------------
__device__ __half g_qh[(size_t)B_ * N_ * D_];
__device__ __half g_ql[(size_t)B_ * N_ * D_];
__device__ __half g_kh[(size_t)B_ * N_ * D_];
__device__ __half g_kl[(size_t)B_ * N_ * D_];
__device__ __half g_v [(size_t)B_ * C_ * N_];
__device__ __half g_xh[(size_t)B_ * C_ * N_];   // x split hi [b][c][n]
__device__ __half g_xl[(size_t)B_ * C_ * N_];   // x split lo
__device__ __half g_wh[320 * 256];              // [Wq;Wk;Wv] split hi
__device__ __half g_wl[320 * 256];

__device__ __forceinline__ uint32_t smem_u32(const void* p) {
    uint32_t a;
    asm("{ .reg .u64 t; cvta.to.shared.u64 t, %1; cvt.u32.u64 %0, t; }" : "=r"(a) : "l"(p));
    return a;
}
__device__ __forceinline__ void ldsm4(uint32_t* r, uint32_t addr) {
    asm volatile("ldmatrix.sync.aligned.m8n8.x4.shared.b16 {%0,%1,%2,%3}, [%4];"
                 : "=r"(r[0]), "=r"(r[1]), "=r"(r[2]), "=r"(r[3]) : "r"(addr));
}
__device__ __forceinline__ void ldsm4t(uint32_t* r, uint32_t addr) {
    asm volatile("ldmatrix.sync.aligned.m8n8.x4.trans.shared.b16 {%0,%1,%2,%3}, [%4];"
                 : "=r"(r[0]), "=r"(r[1]), "=r"(r[2]), "=r"(r[3]) : "r"(addr));
}
__device__ __forceinline__ void mma_f16(float* c, const uint32_t* a, uint32_t b0, uint32_t b1) {
    asm volatile("mma.sync.aligned.m16n8k16.row.col.f32.f16.f16.f32 "
                 "{%0,%1,%2,%3}, {%4,%5,%6,%7}, {%8,%9}, {%0,%1,%2,%3};"
                 : "+f"(c[0]), "+f"(c[1]), "+f"(c[2]), "+f"(c[3])
                 : "r"(a[0]), "r"(a[1]), "r"(a[2]), "r"(a[3]), "r"(b0), "r"(b1));
}
__device__ __forceinline__ void cpa16(uint32_t dst, const void* src) {
    asm volatile("cp.async.cg.shared.global [%0], [%1], 16;" :: "r"(dst), "l"(src));
}
#define CP_COMMIT() asm volatile("cp.async.commit_group;" ::: "memory")
#define CP_WAIT(n)  asm volatile("cp.async.wait_group %0;" :: "n"(n) : "memory")

__device__ __forceinline__ float ex2f(float x) {
    float r; asm("ex2.approx.f32 %0, %1;" : "=f"(r) : "f"(x)); return r;
}

// swizzles: 64B rows (Q/K/W) and 128B rows (V/P)
__device__ __forceinline__ uint32_t sw64(int row, int u)  { return row * 64  + ((u ^ ((row >> 1) & 3)) << 4); }
__device__ __forceinline__ uint32_t sw128(int row, int u) { return row * 128 + ((u ^ (row & 7)) << 4); }

// ldmatrix x4 address helpers
__device__ __forceinline__ uint32_t a64(uint32_t base, int row0, int k16, int lane) {
    int lr = lane & 7, grp = lane >> 3;
    return base + sw64(row0 + lr + (grp & 1) * 8, k16 + (grp >> 1));
}
__device__ __forceinline__ uint32_t b64(uint32_t base, int row0, int k16, int lane) {
    int lr = lane & 7, grp = lane >> 3;
    return base + sw64(row0 + lr + (grp >> 1) * 8, k16 + (grp & 1));
}
__device__ __forceinline__ uint32_t a128(uint32_t base, int row0, int k16, int lane) {
    int lr = lane & 7, grp = lane >> 3;
    return base + sw128(row0 + lr + (grp & 1) * 8, k16 + (grp >> 1));
}
__device__ __forceinline__ uint32_t b128(uint32_t base, int row0, int k16, int lane) {
    int lr = lane & 7, grp = lane >> 3;
    return base + sw128(row0 + lr + (grp >> 1) * 8, k16 + (grp & 1));
}
// B-fragment (trans) from X stored [k][n] (512B rows, k-XOR swizzle on 16B units)
__device__ __forceinline__ uint32_t bxt(uint32_t base, int k0, int n0, int lane) {
    int lr = lane & 7, grp = lane >> 3;
    int k  = k0 + lr + (grp & 1) * 8;
    int un = (n0 >> 3) + (grp >> 1);
    return base + (k * 32 + (un ^ (k & 7))) * 16;
}
__device__ __forceinline__ uint32_t h2pack(float a, float b) {
    __half2 h = __floats2half2_rn(a, b);
    return *reinterpret_cast<uint32_t*>(&h);
}

// ---------------------------------------------------------------------------
// split kernel: x -> g_xh/g_xl, [Wq;Wk;Wv] -> g_wh/g_wl (fp16 hi/lo)
// ---------------------------------------------------------------------------
__global__ __launch_bounds__(256) void split_kernel(
    const float* __restrict__ x,
    const float* __restrict__ Wq, const float* __restrict__ Wk,
    const float* __restrict__ Wv)
{
    const int bid = blockIdx.x;
    const int t   = threadIdx.x;
    if (bid < 4096) {
        size_t base = (size_t)bid * 2048 + (size_t)t * 8;
        float4 v0 = *(const float4*)(x + base);
        float4 v1 = *(const float4*)(x + base + 4);
        float vv[8] = {v0.x, v0.y, v0.z, v0.w, v1.x, v1.y, v1.z, v1.w};
        __half h[8], l[8];
#pragma unroll
        for (int i = 0; i < 8; i++) {
            h[i] = __float2half_rn(vv[i]);
            l[i] = __float2half_rn(vv[i] - __half2float(h[i]));
        }
        *(uint4*)(g_xh + base) = *(uint4*)h;
        *(uint4*)(g_xl + base) = *(uint4*)l;
    } else {
        int idx = (bid - 4096) * 2048 + t * 8;
        if (idx < 320 * 256) {
            int row = idx >> 8, col = idx & 255;
            const float* src;
            if (row < 32)       src = Wq + row * 256 + col;
            else if (row < 64)  src = Wk + (row - 32) * 256 + col;
            else                src = Wv + (row - 64) * 256 + col;
            float4 v0 = *(const float4*)(src);
            float4 v1 = *(const float4*)(src + 4);
            float vv[8] = {v0.x, v0.y, v0.z, v0.w, v1.x, v1.y, v1.z, v1.w};
            __half h[8], l[8];
#pragma unroll
            for (int i = 0; i < 8; i++) {
                h[i] = __float2half_rn(vv[i]);
                l[i] = __float2half_rn(vv[i] - __half2float(h[i]));
            }
            *(uint4*)(g_wh + idx) = *(uint4*)h;
            *(uint4*)(g_wl + idx) = *(uint4*)l;
        }
    }
}

// ---------------------------------------------------------------------------
// qkv via tensor cores: Y = W @ X + bias, 3-term fp16.
// K rows are scaled by log2(e) in the epilogue (log2-domain softmax).
// ---------------------------------------------------------------------------
__global__ __launch_bounds__(256, 2) void qkv_mma(
    const float* __restrict__ bq, const float* __restrict__ bk,
    const float* __restrict__ bv)
{
    extern __shared__ char smem[];
    const uint32_t sb = smem_u32(smem);
    const int t    = threadIdx.x;
    const int w    = t >> 5;
    const int lane = t & 31;
    const int g    = lane >> 2;
    const int tig  = lane & 3;
    const int n0   = blockIdx.x * 256;
    const int row0 = blockIdx.y * 64;
    const int b    = blockIdx.z;
    const int mqw  = (w & 1) * 32;
    const int nw   = (w >> 1) * 64;

    {
        const int k0 = 0;
#pragma unroll
        for (int it = 0; it < 2; it++) {
            int cw = it * THREADS + t;
            int hl = cw >> 8, idx = cw & 255, r = idx >> 2, u = idx & 3;
            const __half* src = (hl ? g_wl : g_wh) + (row0 + r) * 256 + k0 + u * 8;
            cpa16(sb + QSW + hl * 4096 + sw64(r, u), src);
        }
#pragma unroll
        for (int it = 0; it < 8; it++) {
            int cx = it * THREADS + t;
            int hl = cx >> 10, idx = cx & 1023, k = idx >> 5, u = idx & 31;
            const __half* src = (hl ? g_xl : g_xh) + ((size_t)(b * 256 + k0 + k)) * N_ + n0 + u * 8;
            cpa16(sb + QSX + hl * 16384 + (k * 32 + (u ^ (k & 7))) * 16, src);
        }
        CP_COMMIT();
    }

    float o[2][8][4];
#pragma unroll
    for (int mb = 0; mb < 2; mb++)
#pragma unroll
        for (int nb = 0; nb < 8; nb++)
#pragma unroll
            for (int r = 0; r < 4; r++) o[mb][nb][r] = 0.f;

    for (int ck = 0; ck < 8; ck++) {
        const int buf = ck & 1;
        __syncthreads();
        if (ck + 1 < 8) {
            const int k0 = (ck + 1) * 32, bn = (ck + 1) & 1;
#pragma unroll
            for (int it = 0; it < 2; it++) {
                int cw = it * THREADS + t;
                int hl = cw >> 8, idx = cw & 255, r = idx >> 2, u = idx & 3;
                const __half* src = (hl ? g_wl : g_wh) + (row0 + r) * 256 + k0 + u * 8;
                cpa16(sb + QSW + (bn * 2 + hl) * 4096 + sw64(r, u), src);
            }
#pragma unroll
            for (int it = 0; it < 8; it++) {
                int cx = it * THREADS + t;
                int hl = cx >> 10, idx = cx & 1023, k = idx >> 5, u = idx & 31;
                const __half* src = (hl ? g_xl : g_xh) + ((size_t)(b * 256 + k0 + k)) * N_ + n0 + u * 8;
                cpa16(sb + QSX + (bn * 2 + hl) * 16384 + (k * 32 + (u ^ (k & 7))) * 16, src);
            }
            CP_COMMIT();
            CP_WAIT(1);
        } else {
            CP_WAIT(0);
        }
        __syncthreads();

        const uint32_t baseWh = sb + QSW + (buf * 2 + 0) * 4096;
        const uint32_t baseWl = sb + QSW + (buf * 2 + 1) * 4096;
        const uint32_t baseXh = sb + QSX + (buf * 2 + 0) * 16384;
        const uint32_t baseXl = sb + QSX + (buf * 2 + 1) * 16384;

#pragma unroll
        for (int kb = 0; kb < 2; kb++) {
            uint32_t ah[2][4], al[2][4];
            ldsm4(ah[0], a64(baseWh, mqw,      kb * 2, lane));
            ldsm4(ah[1], a64(baseWh, mqw + 16, kb * 2, lane));
            ldsm4(al[0], a64(baseWl, mqw,      kb * 2, lane));
            ldsm4(al[1], a64(baseWl, mqw + 16, kb * 2, lane));
#pragma unroll
            for (int nt = 0; nt < 4; nt++) {
                uint32_t bh[4], bl[4];
                ldsm4t(bh, bxt(baseXh, kb * 16, nw + nt * 16, lane));
                ldsm4t(bl, bxt(baseXl, kb * 16, nw + nt * 16, lane));
#pragma unroll
                for (int mb = 0; mb < 2; mb++) {
                    mma_f16(o[mb][nt * 2 + 0], ah[mb], bh[0], bh[1]);
                    mma_f16(o[mb][nt * 2 + 1], ah[mb], bh[2], bh[3]);
                    mma_f16(o[mb][nt * 2 + 0], ah[mb], bl[0], bl[1]);
                    mma_f16(o[mb][nt * 2 + 1], ah[mb], bl[2], bl[3]);
                    mma_f16(o[mb][nt * 2 + 0], al[mb], bh[0], bh[1]);
                    mma_f16(o[mb][nt * 2 + 1], al[mb], bh[2], bh[3]);
                }
            }
        }
    }

    if (row0 == 0) {
#pragma unroll
        for (int mb = 0; mb < 2; mb++)
#pragma unroll
            for (int hh = 0; hh < 2; hh++) {
                int rg = mqw + mb * 16 + g + hh * 8;
                const bool isq = (rg < 32);
                const int d = isq ? rg : rg - 32;
                const float bias = isq ? bq[rg] : bk[rg - 32];
                const float scale = isq ? 1.f : LOG2E;   // K in log2 domain
                __half* dh = isq ? g_qh : g_kh;
                __half* dl = isq ? g_ql : g_kl;
#pragma unroll
                for (int nb = 0; nb < 8; nb++)
#pragma unroll
                    for (int c2 = 0; c2 < 2; c2++) {
                        float val = (o[mb][nb][hh * 2 + c2] + bias) * scale;
                        int n = n0 + nw + nb * 8 + tig * 2 + c2;
                        __half h = __float2half_rn(val);
                        __half l = __float2half_rn(val - __half2float(h));
                        size_t off = ((size_t)b * N_ + n) * D_ + d;
                        dh[off] = h; dl[off] = l;
                    }
            }
    } else {
#pragma unroll
        for (int mb = 0; mb < 2; mb++)
#pragma unroll
            for (int hh = 0; hh < 2; hh++) {
                int c = row0 - 64 + mqw + mb * 16 + g + hh * 8;
                const float bias = bv[c];
#pragma unroll
                for (int nb = 0; nb < 8; nb++) {
                    float v0 = o[mb][nb][hh * 2 + 0] + bias;
                    float v1 = o[mb][nb][hh * 2 + 1] + bias;
                    int n = n0 + nw + nb * 8 + tig * 2;
                    *(uint32_t*)(g_v + ((size_t)b * C_ + c) * (size_t)N_ + n) = h2pack(v0, v1);
                }
            }
    }
}

// ---------------------------------------------------------------------------
// fp16 flash attention — R10 pipeline; QK uses 2-term split (qh·kh + qh·kl;
// ql term dropped, error diluted ~0.13x through softmax => ~2.6e-4 final);
// softmax in log2 domain (K pre-scaled by log2e, ex2.approx directly).
// 1 CTA per (batch, 64-q tile), 256 thr, 2 CTAs/SM.
// ---------------------------------------------------------------------------
__global__ __launch_bounds__(THREADS, 2) void attn_kernel(
    const float* __restrict__ x, const float* __restrict__ gamma_p,
    float* __restrict__ out)
{
    extern __shared__ char smem[];
    const uint32_t sb = smem_u32(smem);
    const int t    = threadIdx.x;
    const int w    = t >> 5;
    const int lane = t & 31;
    const int g    = lane >> 2;
    const int tig  = lane & 3;
    const int b    = blockIdx.y;
    const int q0   = blockIdx.x * QTILE;
    const int qg   = w & 1;
    const int sl   = w >> 1;
    const int mq   = qg * 32;

    const __half* qhp = g_qh + (size_t)b * N_ * D_;
    const __half* khp = g_kh + (size_t)b * N_ * D_;
    const __half* klp = g_kl + (size_t)b * N_ * D_;
    const __half* vp  = g_v  + (size_t)b * C_ * (size_t)N_;

    // prefetch tile 0: K group, then V group (separate commits!)
#pragma unroll
    for (int it = 0; it < 2; it++) {
        int chunk = it * THREADS + t;
        int hl = chunk >> 8, idx = chunk & 255, row = idx >> 2, u = idx & 3;
        const __half* src = (hl ? klp : khp) + (size_t)row * D_ + u * 8;
        cpa16(sb + SM_K + hl * 4096 + sw64(row, u), src);
    }
    CP_COMMIT();
#pragma unroll
    for (int it = 0; it < 8; it++) {
        int chunk = it * THREADS + t;
        int row = chunk >> 3, u = chunk & 7;
        cpa16(sb + SM_V + sw128(row, u), vp + (size_t)row * N_ + u * 8);
    }
    CP_COMMIT();

    // Q tile (hi only now) plain load: 64 rows x 64B = 256 uint4 chunks
    {
        int chunk = t;
        int row = chunk >> 2, u = chunk & 3;
        const __half* src = qhp + (size_t)(q0 + row) * D_ + u * 8;
        *(uint4*)(smem + SM_Q + sw64(row, u)) = *(const uint4*)src;
    }
    __syncthreads();

    // Q fragments (static across tiles) — hi only
    uint32_t qhf[2][2][4];
#pragma unroll
    for (int mb = 0; mb < 2; mb++)
#pragma unroll
        for (int kb = 0; kb < 2; kb++)
            ldsm4(qhf[mb][kb], a64(sb + SM_Q, mq + mb * 16, kb * 2, lane));

    float o[2][8][4];
#pragma unroll
    for (int mb = 0; mb < 2; mb++)
#pragma unroll
        for (int nb = 0; nb < 8; nb++)
#pragma unroll
            for (int r = 0; r < 4; r++) o[mb][nb][r] = 0.f;

    float lacc[2][2] = {{0.f, 0.f}, {0.f, 0.f}};
    float mold[2][2];

    // ======================= peeled tile 0 =======================
    {
        CP_WAIT(1);          // K(0) done (V(0) may be in flight)
        __syncthreads();
        // prefetch K(1)
#pragma unroll
        for (int it = 0; it < 2; it++) {
            int chunk = it * THREADS + t;
            int hl = chunk >> 8, idx = chunk & 255, row = idx >> 2, u = idx & 3;
            const __half* src = (hl ? klp : khp) + (size_t)(KTILE + row) * D_ + u * 8;
            cpa16(sb + SM_K + (2 + hl) * 4096 + sw64(row, u), src);
        }
        CP_COMMIT();

        // S(0): 2-term
        float s[2][2][4];
#pragma unroll
        for (int mb = 0; mb < 2; mb++)
#pragma unroll
            for (int nb = 0; nb < 2; nb++)
#pragma unroll
                for (int r = 0; r < 4; r++) s[mb][nb][r] = 0.f;
#pragma unroll
        for (int kb = 0; kb < 2; kb++) {
            uint32_t khf[4], klf[4];
            ldsm4(khf, b64(sb + SM_K + 0 * 4096, sl * 16, kb * 2, lane));
            ldsm4(klf, b64(sb + SM_K + 1 * 4096, sl * 16, kb * 2, lane));
#pragma unroll
            for (int mb = 0; mb < 2; mb++)
#pragma unroll
                for (int nb = 0; nb < 2; nb++) {
                    mma_f16(s[mb][nb], qhf[mb][kb], khf[nb * 2], khf[nb * 2 + 1]);
                    mma_f16(s[mb][nb], qhf[mb][kb], klf[nb * 2], klf[nb * 2 + 1]);
                }
        }
        // max
        float mloc[2][2];
#pragma unroll
        for (int mb = 0; mb < 2; mb++) {
            mloc[mb][0] = fmaxf(fmaxf(s[mb][0][0], s[mb][0][1]), fmaxf(s[mb][1][0], s[mb][1][1]));
            mloc[mb][1] = fmaxf(fmaxf(s[mb][0][2], s[mb][0][3]), fmaxf(s[mb][1][2], s[mb][1][3]));
        }
#pragma unroll
        for (int mb = 0; mb < 2; mb++)
#pragma unroll
            for (int hf = 0; hf < 2; hf++) {
                float v = mloc[mb][hf];
                v = fmaxf(v, __shfl_xor_sync(0xffffffffu, v, 1));
                v = fmaxf(v, __shfl_xor_sync(0xffffffffu, v, 2));
                mloc[mb][hf] = v;
            }
        if (tig == 0) {
#pragma unroll
            for (int mb = 0; mb < 2; mb++)
#pragma unroll
                for (int hf = 0; hf < 2; hf++)
                    *(float*)(smem + SM_PM + (mq + mb * 16 + g + hf * 8) * 16 + sl * 4) = mloc[mb][hf];
        }
        __syncthreads();
#pragma unroll
        for (int mb = 0; mb < 2; mb++)
#pragma unroll
            for (int hf = 0; hf < 2; hf++) {
                int row = mq + mb * 16 + g + hf * 8;
                float4 pm = *(const float4*)(smem + SM_PM + row * 16);
                mold[mb][hf] = fmaxf(fmaxf(pm.x, pm.y), fmaxf(pm.z, pm.w));
            }
        // softmax(0) -> P buf 0 (log2 domain)
#pragma unroll
        for (int mb = 0; mb < 2; mb++)
#pragma unroll
            for (int nb = 0; nb < 2; nb++) {
                float e0 = ex2f(s[mb][nb][0] - mold[mb][0]);
                float e1 = ex2f(s[mb][nb][1] - mold[mb][0]);
                float e2 = ex2f(s[mb][nb][2] - mold[mb][1]);
                float e3 = ex2f(s[mb][nb][3] - mold[mb][1]);
                __half2 h01 = __floats2half2_rn(e0, e1);
                __half2 h23 = __floats2half2_rn(e2, e3);
                float2 f01 = __half22float2(h01), f23 = __half22float2(h23);
                lacc[mb][0] += f01.x + f01.y;
                lacc[mb][1] += f23.x + f23.y;
                int r0 = mq + mb * 16 + g;
                int u  = sl * 2 + nb;
                *(uint32_t*)(smem + SM_P + sw128(r0,     u) + tig * 4) = *(uint32_t*)&h01;
                *(uint32_t*)(smem + SM_P + sw128(r0 + 8, u) + tig * 4) = *(uint32_t*)&h23;
            }
        __syncthreads();   // P(0) visible
        // prefetch V(1)
#pragma unroll
        for (int it = 0; it < 8; it++) {
            int chunk = it * THREADS + t;
            int row = chunk >> 3, u = chunk & 7;
            cpa16(sb + SM_V + 32768 + sw128(row, u), vp + (size_t)row * N_ + KTILE + u * 8);
        }
        CP_COMMIT();
    }

    // ======================= main loop t=1..63 =======================
    for (int tile = 1; tile < NTILES; tile++) {
        const int buf = tile & 1;   // K/V/P write buffer; read side uses buf^1
        CP_WAIT(1);                 // K(t) + V(t-1) ready (V(t) may be in flight)
        __syncthreads();

        if (tile + 1 < NTILES) {
            const int jn = (tile + 1) * KTILE, bn = (tile + 1) & 1;
#pragma unroll
            for (int it = 0; it < 2; it++) {
                int chunk = it * THREADS + t;
                int hl = chunk >> 8, idx = chunk & 255, row = idx >> 2, u = idx & 3;
                const __half* src = (hl ? klp : khp) + (size_t)(jn + row) * D_ + u * 8;
                cpa16(sb + SM_K + (bn * 2 + hl) * 4096 + sw64(row, u), src);
            }
        }
        CP_COMMIT();   // K group committed every iteration (possibly empty) to keep order

        // ---- S(t) = Q K^T : 2-term ----
        float s[2][2][4];
#pragma unroll
        for (int mb = 0; mb < 2; mb++)
#pragma unroll
            for (int nb = 0; nb < 2; nb++)
#pragma unroll
                for (int r = 0; r < 4; r++) s[mb][nb][r] = 0.f;
#pragma unroll
        for (int kb = 0; kb < 2; kb++) {
            uint32_t khf[4], klf[4];
            ldsm4(khf, b64(sb + SM_K + (buf * 2 + 0) * 4096, sl * 16, kb * 2, lane));
            ldsm4(klf, b64(sb + SM_K + (buf * 2 + 1) * 4096, sl * 16, kb * 2, lane));
#pragma unroll
            for (int mb = 0; mb < 2; mb++)
#pragma unroll
                for (int nb = 0; nb < 2; nb++) {
                    mma_f16(s[mb][nb], qhf[mb][kb], khf[nb * 2], khf[nb * 2 + 1]);
                    mma_f16(s[mb][nb], qhf[mb][kb], klf[nb * 2], klf[nb * 2 + 1]);
                }
        }

        // ---- row max exchange ----
        float mloc[2][2];
#pragma unroll
        for (int mb = 0; mb < 2; mb++) {
            mloc[mb][0] = fmaxf(fmaxf(s[mb][0][0], s[mb][0][1]), fmaxf(s[mb][1][0], s[mb][1][1]));
            mloc[mb][1] = fmaxf(fmaxf(s[mb][0][2], s[mb][0][3]), fmaxf(s[mb][1][2], s[mb][1][3]));
        }
#pragma unroll
        for (int mb = 0; mb < 2; mb++)
#pragma unroll
            for (int hf = 0; hf < 2; hf++) {
                float v = mloc[mb][hf];
                v = fmaxf(v, __shfl_xor_sync(0xffffffffu, v, 1));
                v = fmaxf(v, __shfl_xor_sync(0xffffffffu, v, 2));
                mloc[mb][hf] = v;
            }
        if (tig == 0) {
#pragma unroll
            for (int mb = 0; mb < 2; mb++)
#pragma unroll
                for (int hf = 0; hf < 2; hf++)
                    *(float*)(smem + SM_PM + (mq + mb * 16 + g + hf * 8) * 16 + sl * 4) = mloc[mb][hf];
        }
        __syncthreads();

        // ---- alpha(t) (log2 domain) ----
        float al[2][2];
#pragma unroll
        for (int mb = 0; mb < 2; mb++)
#pragma unroll
            for (int hf = 0; hf < 2; hf++) {
                int row = mq + mb * 16 + g + hf * 8;
                float4 pm = *(const float4*)(smem + SM_PM + row * 16);
                float mt = fmaxf(fmaxf(pm.x, pm.y), fmaxf(pm.z, pm.w));
                float mn = fmaxf(mold[mb][hf], mt);
                al[mb][hf] = ex2f(mold[mb][hf] - mn);
                mold[mb][hf] = mn;
            }

        // ---- interleaved: PV(t-1) MMAs + softmax(t) exps (independent pipes)
        float lsum[2][2] = {{0.f, 0.f}, {0.f, 0.f}};
        const uint32_t pR = sb + SM_P + (buf ^ 1) * 8192;
        const uint32_t vR = sb + SM_V + (buf ^ 1) * 32768;
        const int pWo = SM_P + buf * 8192;
#pragma unroll
        for (int kb = 0; kb < 4; kb++) {
            uint32_t phf[2][4];
            ldsm4(phf[0], a128(pR, mq,      kb * 2, lane));
            ldsm4(phf[1], a128(pR, mq + 16, kb * 2, lane));
#pragma unroll
            for (int nb2 = 0; nb2 < 4; nb2++) {
                uint32_t vhf[4];
                ldsm4(vhf, b128(vR, sl * 64 + nb2 * 16, kb * 2, lane));
                mma_f16(o[0][nb2 * 2 + 0], phf[0], vhf[0], vhf[1]);
                mma_f16(o[0][nb2 * 2 + 1], phf[0], vhf[2], vhf[3]);
                mma_f16(o[1][nb2 * 2 + 0], phf[1], vhf[0], vhf[1]);
                mma_f16(o[1][nb2 * 2 + 1], phf[1], vhf[2], vhf[3]);
            }
            // softmax chunk (mb,nb) = (kb>>1, kb&1), log2 domain
            {
                const int mb = kb >> 1, nb = kb & 1;
                float e0 = ex2f(s[mb][nb][0] - mold[mb][0]);
                float e1 = ex2f(s[mb][nb][1] - mold[mb][0]);
                float e2 = ex2f(s[mb][nb][2] - mold[mb][1]);
                float e3 = ex2f(s[mb][nb][3] - mold[mb][1]);
                __half2 h01 = __floats2half2_rn(e0, e1);
                __half2 h23 = __floats2half2_rn(e2, e3);
                float2 f01 = __half22float2(h01), f23 = __half22float2(h23);
                lsum[mb][0] += f01.x + f01.y;
                lsum[mb][1] += f23.x + f23.y;
                int r0 = mq + mb * 16 + g;
                int u  = sl * 2 + nb;
                *(uint32_t*)(smem + pWo + sw128(r0,     u) + tig * 4) = *(uint32_t*)&h01;
                *(uint32_t*)(smem + pWo + sw128(r0 + 8, u) + tig * 4) = *(uint32_t*)&h23;
            }
        }
        // rescale to frame m(t): O = (O + PV(t-1)) * alpha
#pragma unroll
        for (int mb = 0; mb < 2; mb++)
#pragma unroll
            for (int nb = 0; nb < 8; nb++) {
                o[mb][nb][0] *= al[mb][0]; o[mb][nb][1] *= al[mb][0];
                o[mb][nb][2] *= al[mb][1]; o[mb][nb][3] *= al[mb][1];
            }
#pragma unroll
        for (int mb = 0; mb < 2; mb++)
#pragma unroll
            for (int hf = 0; hf < 2; hf++)
                lacc[mb][hf] = lacc[mb][hf] * al[mb][hf] + lsum[mb][hf];

        __syncthreads();   // PV(t-1) done (V(t-1) free), P(t) visible

        if (tile + 1 < NTILES) {
            const int jn = (tile + 1) * KTILE, bn = (tile + 1) & 1;
#pragma unroll
            for (int it = 0; it < 8; it++) {
                int chunk = it * THREADS + t;
                int row = chunk >> 3, u = chunk & 7;
                cpa16(sb + SM_V + bn * 32768 + sw128(row, u), vp + (size_t)row * N_ + jn + u * 8);
            }
        }
        CP_COMMIT();   // V group committed every iteration (possibly empty)
    }

    // ======================= drain PV(63) =======================
    CP_WAIT(0);
    __syncthreads();
    {
        const int buf = (NTILES - 1) & 1;   // = 1
        const uint32_t pR = sb + SM_P + buf * 8192;
        const uint32_t vR = sb + SM_V + buf * 32768;
#pragma unroll
        for (int kb = 0; kb < 4; kb++) {
            uint32_t phf[2][4];
            ldsm4(phf[0], a128(pR, mq,      kb * 2, lane));
            ldsm4(phf[1], a128(pR, mq + 16, kb * 2, lane));
#pragma unroll
            for (int nb2 = 0; nb2 < 4; nb2++) {
                uint32_t vhf[4];
                ldsm4(vhf, b128(vR, sl * 64 + nb2 * 16, kb * 2, lane));
                mma_f16(o[0][nb2 * 2 + 0], phf[0], vhf[0], vhf[1]);
                mma_f16(o[0][nb2 * 2 + 1], phf[0], vhf[2], vhf[3]);
                mma_f16(o[1][nb2 * 2 + 0], phf[1], vhf[0], vhf[1]);
                mma_f16(o[1][nb2 * 2 + 1], phf[1], vhf[2], vhf[3]);
            }
        }
    }

    // ---- l reduction: quad shuffle, then cross-warp via smem ----
#pragma unroll
    for (int mb = 0; mb < 2; mb++)
#pragma unroll
        for (int hf = 0; hf < 2; hf++) {
            float v = lacc[mb][hf];
            v += __shfl_xor_sync(0xffffffffu, v, 1);
            v += __shfl_xor_sync(0xffffffffu, v, 2);
            lacc[mb][hf] = v;
        }
    if (tig == 0) {
#pragma unroll
        for (int mb = 0; mb < 2; mb++)
#pragma unroll
            for (int hf = 0; hf < 2; hf++) {
                int row = mq + mb * 16 + g + hf * 8;
                *(float*)(smem + SM_LS + (row * 4 + sl) * 4) = lacc[mb][hf];
            }
    }
    __syncthreads();
    if (t < 64) {
        const float* ls = (const float*)(smem + SM_LS) + t * 4;
        *(float*)(smem + SM_LR + t * 4) = 1.f / (ls[0] + ls[1] + ls[2] + ls[3]);
    }
    __syncthreads();

    // ---- epilogue: out = gamma * O / l + x ----
    {
        const float gma = *gamma_p;
#pragma unroll
        for (int mb = 0; mb < 2; mb++) {
            int r0 = mq + mb * 16 + g;
            int r1 = r0 + 8;
            float li0 = *(const float*)(smem + SM_LR + r0 * 4);
            float li1 = *(const float*)(smem + SM_LR + r1 * 4);
            int i0 = q0 + r0, i1 = q0 + r1;
#pragma unroll
            for (int nb = 0; nb < 8; nb++) {
                int c = sl * 64 + nb * 8 + tig * 2;
                size_t base0 = ((size_t)b * C_ + c) * (size_t)N_;
                size_t base1 = base0 + N_;
                out[base0 + i0] = gma * (o[mb][nb][0] * li0) + x[base0 + i0];
                out[base1 + i0] = gma * (o[mb][nb][1] * li0) + x[base1 + i0];
                out[base0 + i1] = gma * (o[mb][nb][2] * li1) + x[base0 + i1];
                out[base1 + i1] = gma * (o[mb][nb][3] * li1) + x[base1 + i1];
            }
        }
    }
}

extern "C" void kernel_launch(void* const* d_in, const int* in_sizes, int n_in,
                              void* d_out, int out_size) {
    const float* x  = (const float*)d_in[0];
    const float* Wq = (const float*)d_in[1];
    const float* bq = (const float*)d_in[2];
    const float* Wk = (const float*)d_in[3];
    const float* bk = (const float*)d_in[4];
    const float* Wv = (const float*)d_in[5];
    const float* bv = (const float*)d_in[6];
    const float* gm = (const float*)d_in[7];
    float* out = (float*)d_out;

    cudaFuncSetAttribute(qkv_mma, cudaFuncAttributeMaxDynamicSharedMemorySize, QS_TOTAL);
    cudaFuncSetAttribute(attn_kernel, cudaFuncAttributeMaxDynamicSharedMemorySize, SM_TOTAL);

    split_kernel<<<4136, 256>>>(x, Wq, Wk, Wv);
    qkv_mma<<<dim3(16, 5, 8), 256, QS_TOTAL>>>(bq, bk, bv);
    attn_kernel<<<dim3(N_ / QTILE, B_), THREADS, SM_TOTAL>>>(x, gm, out);
}

// round 16
// speedup vs baseline: 1.2512x; 1.0600x over previous
#include <cuda_runtime.h>
#include <cuda_fp16.h>
#include <cstdint>

#define B_ 8
#define C_ 256
#define D_ 32
#define N_ 4096
#define QTILE 64
#define KTILE 64
#define NTILES (N_ / KTILE)
#define THREADS 256
#define LOG2E 1.4426950408889634f

// attn smem byte offsets
#define SM_Q  0                         // Q hi: 64 x 64B (SW64)        = 4096
#define SM_K  4096                      // K[buf]: 2 x 4096 (SW64)      = 8192
#define SM_V  12288                     // V[buf]: 2 x 32768 (SW128)    = 65536
#define SM_P  77824                     // P[buf]: 2 x 8192 (SW128)     = 16384
#define SM_PM 94208                     // pmax[64][4] floats           = 1024
#define SM_LS 95232                     // lsum[64][4] floats           = 1024
#define SM_LR 96256                     // lrecip[64] floats            = 256
#define SM_TOTAL 96512

// qkv_mma smem: W [buf2][hl2][4KB] + X [buf2][hl2][16KB]
#define QSW 0
#define QSX 16384
#define QS_TOTAL 81920

// ---------------------------------------------------------------------------
// scratch (allocation-free rule: device globals)
// ---------------------------------------------------------------------------
__device__ __half g_qh[(size_t)B_ * N_ * D_];
__device__ __half g_kh[(size_t)B_ * N_ * D_];
__device__ __half g_v [(size_t)B_ * C_ * N_];
__device__ __half g_xh[(size_t)B_ * C_ * N_];   // x split hi [b][c][n]
__device__ __half g_xl[(size_t)B_ * C_ * N_];   // x split lo
__device__ __half g_wh[320 * 256];              // [Wq;Wk;Wv] split hi
__device__ __half g_wl[320 * 256];

__device__ __forceinline__ uint32_t smem_u32(const void* p) {
    uint32_t a;
    asm("{ .reg .u64 t; cvta.to.shared.u64 t, %1; cvt.u32.u64 %0, t; }" : "=r"(a) : "l"(p));
    return a;
}
__device__ __forceinline__ void ldsm4(uint32_t* r, uint32_t addr) {
    asm volatile("ldmatrix.sync.aligned.m8n8.x4.shared.b16 {%0,%1,%2,%3}, [%4];"
                 : "=r"(r[0]), "=r"(r[1]), "=r"(r[2]), "=r"(r[3]) : "r"(addr));
}
__device__ __forceinline__ void ldsm4t(uint32_t* r, uint32_t addr) {
    asm volatile("ldmatrix.sync.aligned.m8n8.x4.trans.shared.b16 {%0,%1,%2,%3}, [%4];"
                 : "=r"(r[0]), "=r"(r[1]), "=r"(r[2]), "=r"(r[3]) : "r"(addr));
}
__device__ __forceinline__ void mma_f16(float* c, const uint32_t* a, uint32_t b0, uint32_t b1) {
    asm volatile("mma.sync.aligned.m16n8k16.row.col.f32.f16.f16.f32 "
                 "{%0,%1,%2,%3}, {%4,%5,%6,%7}, {%8,%9}, {%0,%1,%2,%3};"
                 : "+f"(c[0]), "+f"(c[1]), "+f"(c[2]), "+f"(c[3])
                 : "r"(a[0]), "r"(a[1]), "r"(a[2]), "r"(a[3]), "r"(b0), "r"(b1));
}
__device__ __forceinline__ void cpa16(uint32_t dst, const void* src) {
    asm volatile("cp.async.cg.shared.global [%0], [%1], 16;" :: "r"(dst), "l"(src));
}
#define CP_COMMIT() asm volatile("cp.async.commit_group;" ::: "memory")
#define CP_WAIT(n)  asm volatile("cp.async.wait_group %0;" :: "n"(n) : "memory")

__device__ __forceinline__ float ex2f(float x) {
    float r; asm("ex2.approx.f32 %0, %1;" : "=f"(r) : "f"(x)); return r;
}

// swizzles: 64B rows (Q/K/W) and 128B rows (V/P)
__device__ __forceinline__ uint32_t sw64(int row, int u)  { return row * 64  + ((u ^ ((row >> 1) & 3)) << 4); }
__device__ __forceinline__ uint32_t sw128(int row, int u) { return row * 128 + ((u ^ (row & 7)) << 4); }

// ldmatrix x4 address helpers
__device__ __forceinline__ uint32_t a64(uint32_t base, int row0, int k16, int lane) {
    int lr = lane & 7, grp = lane >> 3;
    return base + sw64(row0 + lr + (grp & 1) * 8, k16 + (grp >> 1));
}
__device__ __forceinline__ uint32_t b64(uint32_t base, int row0, int k16, int lane) {
    int lr = lane & 7, grp = lane >> 3;
    return base + sw64(row0 + lr + (grp >> 1) * 8, k16 + (grp & 1));
}
__device__ __forceinline__ uint32_t a128(uint32_t base, int row0, int k16, int lane) {
    int lr = lane & 7, grp = lane >> 3;
    return base + sw128(row0 + lr + (grp & 1) * 8, k16 + (grp >> 1));
}
__device__ __forceinline__ uint32_t b128(uint32_t base, int row0, int k16, int lane) {
    int lr = lane & 7, grp = lane >> 3;
    return base + sw128(row0 + lr + (grp >> 1) * 8, k16 + (grp & 1));
}
// B-fragment (trans) from X stored [k][n] (512B rows, k-XOR swizzle on 16B units)
__device__ __forceinline__ uint32_t bxt(uint32_t base, int k0, int n0, int lane) {
    int lr = lane & 7, grp = lane >> 3;
    int k  = k0 + lr + (grp & 1) * 8;
    int un = (n0 >> 3) + (grp >> 1);
    return base + (k * 32 + (un ^ (k & 7))) * 16;
}
__device__ __forceinline__ uint32_t h2pack(float a, float b) {
    __half2 h = __floats2half2_rn(a, b);
    return *reinterpret_cast<uint32_t*>(&h);
}

// ---------------------------------------------------------------------------
// split kernel: x -> g_xh/g_xl, [Wq;Wk;Wv] -> g_wh/g_wl (fp16 hi/lo)
// ---------------------------------------------------------------------------
__global__ __launch_bounds__(256) void split_kernel(
    const float* __restrict__ x,
    const float* __restrict__ Wq, const float* __restrict__ Wk,
    const float* __restrict__ Wv)
{
    const int bid = blockIdx.x;
    const int t   = threadIdx.x;
    if (bid < 4096) {
        size_t base = (size_t)bid * 2048 + (size_t)t * 8;
        float4 v0 = *(const float4*)(x + base);
        float4 v1 = *(const float4*)(x + base + 4);
        float vv[8] = {v0.x, v0.y, v0.z, v0.w, v1.x, v1.y, v1.z, v1.w};
        __half h[8], l[8];
#pragma unroll
        for (int i = 0; i < 8; i++) {
            h[i] = __float2half_rn(vv[i]);
            l[i] = __float2half_rn(vv[i] - __half2float(h[i]));
        }
        *(uint4*)(g_xh + base) = *(uint4*)h;
        *(uint4*)(g_xl + base) = *(uint4*)l;
    } else {
        int idx = (bid - 4096) * 2048 + t * 8;
        if (idx < 320 * 256) {
            int row = idx >> 8, col = idx & 255;
            const float* src;
            if (row < 32)       src = Wq + row * 256 + col;
            else if (row < 64)  src = Wk + (row - 32) * 256 + col;
            else                src = Wv + (row - 64) * 256 + col;
            float4 v0 = *(const float4*)(src);
            float4 v1 = *(const float4*)(src + 4);
            float vv[8] = {v0.x, v0.y, v0.z, v0.w, v1.x, v1.y, v1.z, v1.w};
            __half h[8], l[8];
#pragma unroll
            for (int i = 0; i < 8; i++) {
                h[i] = __float2half_rn(vv[i]);
                l[i] = __float2half_rn(vv[i] - __half2float(h[i]));
            }
            *(uint4*)(g_wh + idx) = *(uint4*)h;
            *(uint4*)(g_wl + idx) = *(uint4*)l;
        }
    }
}

// ---------------------------------------------------------------------------
// qkv via tensor cores: Y = W @ X + bias, 3-term fp16.
// K rows are scaled by log2(e) in the epilogue (log2-domain softmax).
// q/k stored as SINGLE fp16 (hi only) — single-term QK in attention.
// ---------------------------------------------------------------------------
__global__ __launch_bounds__(256, 2) void qkv_mma(
    const float* __restrict__ bq, const float* __restrict__ bk,
    const float* __restrict__ bv)
{
    extern __shared__ char smem[];
    const uint32_t sb = smem_u32(smem);
    const int t    = threadIdx.x;
    const int w    = t >> 5;
    const int lane = t & 31;
    const int g    = lane >> 2;
    const int tig  = lane & 3;
    const int n0   = blockIdx.x * 256;
    const int row0 = blockIdx.y * 64;
    const int b    = blockIdx.z;
    const int mqw  = (w & 1) * 32;
    const int nw   = (w >> 1) * 64;

    {
        const int k0 = 0;
#pragma unroll
        for (int it = 0; it < 2; it++) {
            int cw = it * THREADS + t;
            int hl = cw >> 8, idx = cw & 255, r = idx >> 2, u = idx & 3;
            const __half* src = (hl ? g_wl : g_wh) + (row0 + r) * 256 + k0 + u * 8;
            cpa16(sb + QSW + hl * 4096 + sw64(r, u), src);
        }
#pragma unroll
        for (int it = 0; it < 8; it++) {
            int cx = it * THREADS + t;
            int hl = cx >> 10, idx = cx & 1023, k = idx >> 5, u = idx & 31;
            const __half* src = (hl ? g_xl : g_xh) + ((size_t)(b * 256 + k0 + k)) * N_ + n0 + u * 8;
            cpa16(sb + QSX + hl * 16384 + (k * 32 + (u ^ (k & 7))) * 16, src);
        }
        CP_COMMIT();
    }

    float o[2][8][4];
#pragma unroll
    for (int mb = 0; mb < 2; mb++)
#pragma unroll
        for (int nb = 0; nb < 8; nb++)
#pragma unroll
            for (int r = 0; r < 4; r++) o[mb][nb][r] = 0.f;

    for (int ck = 0; ck < 8; ck++) {
        const int buf = ck & 1;
        __syncthreads();
        if (ck + 1 < 8) {
            const int k0 = (ck + 1) * 32, bn = (ck + 1) & 1;
#pragma unroll
            for (int it = 0; it < 2; it++) {
                int cw = it * THREADS + t;
                int hl = cw >> 8, idx = cw & 255, r = idx >> 2, u = idx & 3;
                const __half* src = (hl ? g_wl : g_wh) + (row0 + r) * 256 + k0 + u * 8;
                cpa16(sb + QSW + (bn * 2 + hl) * 4096 + sw64(r, u), src);
            }
#pragma unroll
            for (int it = 0; it < 8; it++) {
                int cx = it * THREADS + t;
                int hl = cx >> 10, idx = cx & 1023, k = idx >> 5, u = idx & 31;
                const __half* src = (hl ? g_xl : g_xh) + ((size_t)(b * 256 + k0 + k)) * N_ + n0 + u * 8;
                cpa16(sb + QSX + (bn * 2 + hl) * 16384 + (k * 32 + (u ^ (k & 7))) * 16, src);
            }
            CP_COMMIT();
            CP_WAIT(1);
        } else {
            CP_WAIT(0);
        }
        __syncthreads();

        const uint32_t baseWh = sb + QSW + (buf * 2 + 0) * 4096;
        const uint32_t baseWl = sb + QSW + (buf * 2 + 1) * 4096;
        const uint32_t baseXh = sb + QSX + (buf * 2 + 0) * 16384;
        const uint32_t baseXl = sb + QSX + (buf * 2 + 1) * 16384;

#pragma unroll
        for (int kb = 0; kb < 2; kb++) {
            uint32_t ah[2][4], al[2][4];
            ldsm4(ah[0], a64(baseWh, mqw,      kb * 2, lane));
            ldsm4(ah[1], a64(baseWh, mqw + 16, kb * 2, lane));
            ldsm4(al[0], a64(baseWl, mqw,      kb * 2, lane));
            ldsm4(al[1], a64(baseWl, mqw + 16, kb * 2, lane));
#pragma unroll
            for (int nt = 0; nt < 4; nt++) {
                uint32_t bh[4], bl[4];
                ldsm4t(bh, bxt(baseXh, kb * 16, nw + nt * 16, lane));
                ldsm4t(bl, bxt(baseXl, kb * 16, nw + nt * 16, lane));
#pragma unroll
                for (int mb = 0; mb < 2; mb++) {
                    mma_f16(o[mb][nt * 2 + 0], ah[mb], bh[0], bh[1]);
                    mma_f16(o[mb][nt * 2 + 1], ah[mb], bh[2], bh[3]);
                    mma_f16(o[mb][nt * 2 + 0], ah[mb], bl[0], bl[1]);
                    mma_f16(o[mb][nt * 2 + 1], ah[mb], bl[2], bl[3]);
                    mma_f16(o[mb][nt * 2 + 0], al[mb], bh[0], bh[1]);
                    mma_f16(o[mb][nt * 2 + 1], al[mb], bh[2], bh[3]);
                }
            }
        }
    }

    if (row0 == 0) {
#pragma unroll
        for (int mb = 0; mb < 2; mb++)
#pragma unroll
            for (int hh = 0; hh < 2; hh++) {
                int rg = mqw + mb * 16 + g + hh * 8;
                const bool isq = (rg < 32);
                const int d = isq ? rg : rg - 32;
                const float bias = isq ? bq[rg] : bk[rg - 32];
                const float scale = isq ? 1.f : LOG2E;   // K in log2 domain
                __half* dh = isq ? g_qh : g_kh;
#pragma unroll
                for (int nb = 0; nb < 8; nb++)
#pragma unroll
                    for (int c2 = 0; c2 < 2; c2++) {
                        float val = (o[mb][nb][hh * 2 + c2] + bias) * scale;
                        int n = n0 + nw + nb * 8 + tig * 2 + c2;
                        dh[((size_t)b * N_ + n) * D_ + d] = __float2half_rn(val);
                    }
            }
    } else {
#pragma unroll
        for (int mb = 0; mb < 2; mb++)
#pragma unroll
            for (int hh = 0; hh < 2; hh++) {
                int c = row0 - 64 + mqw + mb * 16 + g + hh * 8;
                const float bias = bv[c];
#pragma unroll
                for (int nb = 0; nb < 8; nb++) {
                    float v0 = o[mb][nb][hh * 2 + 0] + bias;
                    float v1 = o[mb][nb][hh * 2 + 1] + bias;
                    int n = n0 + nw + nb * 8 + tig * 2;
                    *(uint32_t*)(g_v + ((size_t)b * C_ + c) * (size_t)N_ + n) = h2pack(v0, v1);
                }
            }
    }
}

// ---------------------------------------------------------------------------
// fp16 flash attention — R15 pipeline with SINGLE-TERM QK (qh·kh only;
// measured per-dropped-term error 1.63e-4 => total ~2.4e-4, 4x margin).
// log2-domain softmax (K pre-scaled by log2e, ex2.approx).
// 1 CTA per (batch, 64-q tile), 256 thr, 2 CTAs/SM.
// ---------------------------------------------------------------------------
__global__ __launch_bounds__(THREADS, 2) void attn_kernel(
    const float* __restrict__ x, const float* __restrict__ gamma_p,
    float* __restrict__ out)
{
    extern __shared__ char smem[];
    const uint32_t sb = smem_u32(smem);
    const int t    = threadIdx.x;
    const int w    = t >> 5;
    const int lane = t & 31;
    const int g    = lane >> 2;
    const int tig  = lane & 3;
    const int b    = blockIdx.y;
    const int q0   = blockIdx.x * QTILE;
    const int qg   = w & 1;
    const int sl   = w >> 1;
    const int mq   = qg * 32;

    const __half* qhp = g_qh + (size_t)b * N_ * D_;
    const __half* khp = g_kh + (size_t)b * N_ * D_;
    const __half* vp  = g_v  + (size_t)b * C_ * (size_t)N_;

    // prefetch tile 0: K group, then V group (separate commits!)
    {
        int row = t >> 2, u = t & 3;
        cpa16(sb + SM_K + sw64(row, u), khp + (size_t)row * D_ + u * 8);
    }
    CP_COMMIT();
#pragma unroll
    for (int it = 0; it < 8; it++) {
        int chunk = it * THREADS + t;
        int row = chunk >> 3, u = chunk & 7;
        cpa16(sb + SM_V + sw128(row, u), vp + (size_t)row * N_ + u * 8);
    }
    CP_COMMIT();

    // Q tile (hi only) plain load: 64 rows x 64B = 256 uint4 chunks
    {
        int row = t >> 2, u = t & 3;
        const __half* src = qhp + (size_t)(q0 + row) * D_ + u * 8;
        *(uint4*)(smem + SM_Q + sw64(row, u)) = *(const uint4*)src;
    }
    __syncthreads();

    // Q fragments (static across tiles) — hi only
    uint32_t qhf[2][2][4];
#pragma unroll
    for (int mb = 0; mb < 2; mb++)
#pragma unroll
        for (int kb = 0; kb < 2; kb++)
            ldsm4(qhf[mb][kb], a64(sb + SM_Q, mq + mb * 16, kb * 2, lane));

    float o[2][8][4];
#pragma unroll
    for (int mb = 0; mb < 2; mb++)
#pragma unroll
        for (int nb = 0; nb < 8; nb++)
#pragma unroll
            for (int r = 0; r < 4; r++) o[mb][nb][r] = 0.f;

    float lacc[2][2] = {{0.f, 0.f}, {0.f, 0.f}};
    float mold[2][2];

    // ======================= peeled tile 0 =======================
    {
        CP_WAIT(1);          // K(0) done (V(0) may be in flight)
        __syncthreads();
        // prefetch K(1)
        {
            int row = t >> 2, u = t & 3;
            cpa16(sb + SM_K + 4096 + sw64(row, u), khp + (size_t)(KTILE + row) * D_ + u * 8);
        }
        CP_COMMIT();

        // S(0): single term
        float s[2][2][4];
#pragma unroll
        for (int mb = 0; mb < 2; mb++)
#pragma unroll
            for (int nb = 0; nb < 2; nb++)
#pragma unroll
                for (int r = 0; r < 4; r++) s[mb][nb][r] = 0.f;
#pragma unroll
        for (int kb = 0; kb < 2; kb++) {
            uint32_t khf[4];
            ldsm4(khf, b64(sb + SM_K, sl * 16, kb * 2, lane));
#pragma unroll
            for (int mb = 0; mb < 2; mb++)
#pragma unroll
                for (int nb = 0; nb < 2; nb++)
                    mma_f16(s[mb][nb], qhf[mb][kb], khf[nb * 2], khf[nb * 2 + 1]);
        }
        // max
        float mloc[2][2];
#pragma unroll
        for (int mb = 0; mb < 2; mb++) {
            mloc[mb][0] = fmaxf(fmaxf(s[mb][0][0], s[mb][0][1]), fmaxf(s[mb][1][0], s[mb][1][1]));
            mloc[mb][1] = fmaxf(fmaxf(s[mb][0][2], s[mb][0][3]), fmaxf(s[mb][1][2], s[mb][1][3]));
        }
#pragma unroll
        for (int mb = 0; mb < 2; mb++)
#pragma unroll
            for (int hf = 0; hf < 2; hf++) {
                float v = mloc[mb][hf];
                v = fmaxf(v, __shfl_xor_sync(0xffffffffu, v, 1));
                v = fmaxf(v, __shfl_xor_sync(0xffffffffu, v, 2));
                mloc[mb][hf] = v;
            }
        if (tig == 0) {
#pragma unroll
            for (int mb = 0; mb < 2; mb++)
#pragma unroll
                for (int hf = 0; hf < 2; hf++)
                    *(float*)(smem + SM_PM + (mq + mb * 16 + g + hf * 8) * 16 + sl * 4) = mloc[mb][hf];
        }
        __syncthreads();
#pragma unroll
        for (int mb = 0; mb < 2; mb++)
#pragma unroll
            for (int hf = 0; hf < 2; hf++) {
                int row = mq + mb * 16 + g + hf * 8;
                float4 pm = *(const float4*)(smem + SM_PM + row * 16);
                mold[mb][hf] = fmaxf(fmaxf(pm.x, pm.y), fmaxf(pm.z, pm.w));
            }
        // softmax(0) -> P buf 0 (log2 domain)
#pragma unroll
        for (int mb = 0; mb < 2; mb++)
#pragma unroll
            for (int nb = 0; nb < 2; nb++) {
                float e0 = ex2f(s[mb][nb][0] - mold[mb][0]);
                float e1 = ex2f(s[mb][nb][1] - mold[mb][0]);
                float e2 = ex2f(s[mb][nb][2] - mold[mb][1]);
                float e3 = ex2f(s[mb][nb][3] - mold[mb][1]);
                __half2 h01 = __floats2half2_rn(e0, e1);
                __half2 h23 = __floats2half2_rn(e2, e3);
                float2 f01 = __half22float2(h01), f23 = __half22float2(h23);
                lacc[mb][0] += f01.x + f01.y;
                lacc[mb][1] += f23.x + f23.y;
                int r0 = mq + mb * 16 + g;
                int u  = sl * 2 + nb;
                *(uint32_t*)(smem + SM_P + sw128(r0,     u) + tig * 4) = *(uint32_t*)&h01;
                *(uint32_t*)(smem + SM_P + sw128(r0 + 8, u) + tig * 4) = *(uint32_t*)&h23;
            }
        __syncthreads();   // P(0) visible
        // prefetch V(1)
#pragma unroll
        for (int it = 0; it < 8; it++) {
            int chunk = it * THREADS + t;
            int row = chunk >> 3, u = chunk & 7;
            cpa16(sb + SM_V + 32768 + sw128(row, u), vp + (size_t)row * N_ + KTILE + u * 8);
        }
        CP_COMMIT();
    }

    // ======================= main loop t=1..63 =======================
    for (int tile = 1; tile < NTILES; tile++) {
        const int buf = tile & 1;   // K/V/P write buffer; read side uses buf^1
        CP_WAIT(1);                 // K(t) + V(t-1) ready (V(t) may be in flight)
        __syncthreads();

        if (tile + 1 < NTILES) {
            const int jn = (tile + 1) * KTILE, bn = (tile + 1) & 1;
            int row = t >> 2, u = t & 3;
            cpa16(sb + SM_K + bn * 4096 + sw64(row, u), khp + (size_t)(jn + row) * D_ + u * 8);
        }
        CP_COMMIT();   // K group committed every iteration (possibly empty) to keep order

        // ---- S(t) = Q K^T : single term ----
        float s[2][2][4];
#pragma unroll
        for (int mb = 0; mb < 2; mb++)
#pragma unroll
            for (int nb = 0; nb < 2; nb++)
#pragma unroll
                for (int r = 0; r < 4; r++) s[mb][nb][r] = 0.f;
#pragma unroll
        for (int kb = 0; kb < 2; kb++) {
            uint32_t khf[4];
            ldsm4(khf, b64(sb + SM_K + buf * 4096, sl * 16, kb * 2, lane));
#pragma unroll
            for (int mb = 0; mb < 2; mb++)
#pragma unroll
                for (int nb = 0; nb < 2; nb++)
                    mma_f16(s[mb][nb], qhf[mb][kb], khf[nb * 2], khf[nb * 2 + 1]);
        }

        // ---- row max exchange ----
        float mloc[2][2];
#pragma unroll
        for (int mb = 0; mb < 2; mb++) {
            mloc[mb][0] = fmaxf(fmaxf(s[mb][0][0], s[mb][0][1]), fmaxf(s[mb][1][0], s[mb][1][1]));
            mloc[mb][1] = fmaxf(fmaxf(s[mb][0][2], s[mb][0][3]), fmaxf(s[mb][1][2], s[mb][1][3]));
        }
#pragma unroll
        for (int mb = 0; mb < 2; mb++)
#pragma unroll
            for (int hf = 0; hf < 2; hf++) {
                float v = mloc[mb][hf];
                v = fmaxf(v, __shfl_xor_sync(0xffffffffu, v, 1));
                v = fmaxf(v, __shfl_xor_sync(0xffffffffu, v, 2));
                mloc[mb][hf] = v;
            }
        if (tig == 0) {
#pragma unroll
            for (int mb = 0; mb < 2; mb++)
#pragma unroll
                for (int hf = 0; hf < 2; hf++)
                    *(float*)(smem + SM_PM + (mq + mb * 16 + g + hf * 8) * 16 + sl * 4) = mloc[mb][hf];
        }
        __syncthreads();

        // ---- alpha(t) (log2 domain) ----
        float al[2][2];
#pragma unroll
        for (int mb = 0; mb < 2; mb++)
#pragma unroll
            for (int hf = 0; hf < 2; hf++) {
                int row = mq + mb * 16 + g + hf * 8;
                float4 pm = *(const float4*)(smem + SM_PM + row * 16);
                float mt = fmaxf(fmaxf(pm.x, pm.y), fmaxf(pm.z, pm.w));
                float mn = fmaxf(mold[mb][hf], mt);
                al[mb][hf] = ex2f(mold[mb][hf] - mn);
                mold[mb][hf] = mn;
            }

        // ---- interleaved: PV(t-1) MMAs + softmax(t) exps (independent pipes)
        float lsum[2][2] = {{0.f, 0.f}, {0.f, 0.f}};
        const uint32_t pR = sb + SM_P + (buf ^ 1) * 8192;
        const uint32_t vR = sb + SM_V + (buf ^ 1) * 32768;
        const int pWo = SM_P + buf * 8192;
#pragma unroll
        for (int kb = 0; kb < 4; kb++) {
            uint32_t phf[2][4];
            ldsm4(phf[0], a128(pR, mq,      kb * 2, lane));
            ldsm4(phf[1], a128(pR, mq + 16, kb * 2, lane));
#pragma unroll
            for (int nb2 = 0; nb2 < 4; nb2++) {
                uint32_t vhf[4];
                ldsm4(vhf, b128(vR, sl * 64 + nb2 * 16, kb * 2, lane));
                mma_f16(o[0][nb2 * 2 + 0], phf[0], vhf[0], vhf[1]);
                mma_f16(o[0][nb2 * 2 + 1], phf[0], vhf[2], vhf[3]);
                mma_f16(o[1][nb2 * 2 + 0], phf[1], vhf[0], vhf[1]);
                mma_f16(o[1][nb2 * 2 + 1], phf[1], vhf[2], vhf[3]);
            }
            // softmax chunk (mb,nb) = (kb>>1, kb&1), log2 domain
            {
                const int mb = kb >> 1, nb = kb & 1;
                float e0 = ex2f(s[mb][nb][0] - mold[mb][0]);
                float e1 = ex2f(s[mb][nb][1] - mold[mb][0]);
                float e2 = ex2f(s[mb][nb][2] - mold[mb][1]);
                float e3 = ex2f(s[mb][nb][3] - mold[mb][1]);
                __half2 h01 = __floats2half2_rn(e0, e1);
                __half2 h23 = __floats2half2_rn(e2, e3);
                float2 f01 = __half22float2(h01), f23 = __half22float2(h23);
                lsum[mb][0] += f01.x + f01.y;
                lsum[mb][1] += f23.x + f23.y;
                int r0 = mq + mb * 16 + g;
                int u  = sl * 2 + nb;
                *(uint32_t*)(smem + pWo + sw128(r0,     u) + tig * 4) = *(uint32_t*)&h01;
                *(uint32_t*)(smem + pWo + sw128(r0 + 8, u) + tig * 4) = *(uint32_t*)&h23;
            }
        }
        // rescale to frame m(t): O = (O + PV(t-1)) * alpha
#pragma unroll
        for (int mb = 0; mb < 2; mb++)
#pragma unroll
            for (int nb = 0; nb < 8; nb++) {
                o[mb][nb][0] *= al[mb][0]; o[mb][nb][1] *= al[mb][0];
                o[mb][nb][2] *= al[mb][1]; o[mb][nb][3] *= al[mb][1];
            }
#pragma unroll
        for (int mb = 0; mb < 2; mb++)
#pragma unroll
            for (int hf = 0; hf < 2; hf++)
                lacc[mb][hf] = lacc[mb][hf] * al[mb][hf] + lsum[mb][hf];

        __syncthreads();   // PV(t-1) done (V(t-1) free), P(t) visible

        if (tile + 1 < NTILES) {
            const int jn = (tile + 1) * KTILE, bn = (tile + 1) & 1;
#pragma unroll
            for (int it = 0; it < 8; it++) {
                int chunk = it * THREADS + t;
                int row = chunk >> 3, u = chunk & 7;
                cpa16(sb + SM_V + bn * 32768 + sw128(row, u), vp + (size_t)row * N_ + jn + u * 8);
            }
        }
        CP_COMMIT();   // V group committed every iteration (possibly empty)
    }

    // ======================= drain PV(63) =======================
    CP_WAIT(0);
    __syncthreads();
    {
        const int buf = (NTILES - 1) & 1;   // = 1
        const uint32_t pR = sb + SM_P + buf * 8192;
        const uint32_t vR = sb + SM_V + buf * 32768;
#pragma unroll
        for (int kb = 0; kb < 4; kb++) {
            uint32_t phf[2][4];
            ldsm4(phf[0], a128(pR, mq,      kb * 2, lane));
            ldsm4(phf[1], a128(pR, mq + 16, kb * 2, lane));
#pragma unroll
            for (int nb2 = 0; nb2 < 4; nb2++) {
                uint32_t vhf[4];
                ldsm4(vhf, b128(vR, sl * 64 + nb2 * 16, kb * 2, lane));
                mma_f16(o[0][nb2 * 2 + 0], phf[0], vhf[0], vhf[1]);
                mma_f16(o[0][nb2 * 2 + 1], phf[0], vhf[2], vhf[3]);
                mma_f16(o[1][nb2 * 2 + 0], phf[1], vhf[0], vhf[1]);
                mma_f16(o[1][nb2 * 2 + 1], phf[1], vhf[2], vhf[3]);
            }
        }
    }

    // ---- l reduction: quad shuffle, then cross-warp via smem ----
#pragma unroll
    for (int mb = 0; mb < 2; mb++)
#pragma unroll
        for (int hf = 0; hf < 2; hf++) {
            float v = lacc[mb][hf];
            v += __shfl_xor_sync(0xffffffffu, v, 1);
            v += __shfl_xor_sync(0xffffffffu, v, 2);
            lacc[mb][hf] = v;
        }
    if (tig == 0) {
#pragma unroll
        for (int mb = 0; mb < 2; mb++)
#pragma unroll
            for (int hf = 0; hf < 2; hf++) {
                int row = mq + mb * 16 + g + hf * 8;
                *(float*)(smem + SM_LS + (row * 4 + sl) * 4) = lacc[mb][hf];
            }
    }
    __syncthreads();
    if (t < 64) {
        const float* ls = (const float*)(smem + SM_LS) + t * 4;
        *(float*)(smem + SM_LR + t * 4) = 1.f / (ls[0] + ls[1] + ls[2] + ls[3]);
    }
    __syncthreads();

    // ---- epilogue: out = gamma * O / l + x ----
    {
        const float gma = *gamma_p;
#pragma unroll
        for (int mb = 0; mb < 2; mb++) {
            int r0 = mq + mb * 16 + g;
            int r1 = r0 + 8;
            float li0 = *(const float*)(smem + SM_LR + r0 * 4);
            float li1 = *(const float*)(smem + SM_LR + r1 * 4);
            int i0 = q0 + r0, i1 = q0 + r1;
#pragma unroll
            for (int nb = 0; nb < 8; nb++) {
                int c = sl * 64 + nb * 8 + tig * 2;
                size_t base0 = ((size_t)b * C_ + c) * (size_t)N_;
                size_t base1 = base0 + N_;
                out[base0 + i0] = gma * (o[mb][nb][0] * li0) + x[base0 + i0];
                out[base1 + i0] = gma * (o[mb][nb][1] * li0) + x[base1 + i0];
                out[base0 + i1] = gma * (o[mb][nb][2] * li1) + x[base0 + i1];
                out[base1 + i1] = gma * (o[mb][nb][3] * li1) + x[base1 + i1];
            }
        }
    }
}

extern "C" void kernel_launch(void* const* d_in, const int* in_sizes, int n_in,
                              void* d_out, int out_size) {
    const float* x  = (const float*)d_in[0];
    const float* Wq = (const float*)d_in[1];
    const float* bq = (const float*)d_in[2];
    const float* Wk = (const float*)d_in[3];
    const float* bk = (const float*)d_in[4];
    const float* Wv = (const float*)d_in[5];
    const float* bv = (const float*)d_in[6];
    const float* gm = (const float*)d_in[7];
    float* out = (float*)d_out;

    cudaFuncSetAttribute(qkv_mma, cudaFuncAttributeMaxDynamicSharedMemorySize, QS_TOTAL);
    cudaFuncSetAttribute(attn_kernel, cudaFuncAttributeMaxDynamicSharedMemorySize, SM_TOTAL);

    split_kernel<<<4136, 256>>>(x, Wq, Wk, Wv);
    qkv_mma<<<dim3(16, 5, 8), 256, QS_TOTAL>>>(bq, bk, bv);
    attn_kernel<<<dim3(N_ / QTILE, B_), THREADS, SM_TOTAL>>>(x, gm, out);
}

// round 17
// speedup vs baseline: 1.2910x; 1.0318x over previous
#include <cuda_runtime.h>
#include <cuda_fp16.h>
#include <cstdint>

#define B_ 8
#define C_ 256
#define D_ 32
#define N_ 4096
#define QTILE 64
#define KTILE 64
#define NTILES (N_ / KTILE)
#define THREADS 256
#define LOG2E 1.4426950408889634f

// attn smem byte offsets
#define SM_Q  0                         // Q hi: 64 x 64B (SW64)        = 4096
#define SM_K  4096                      // K[buf]: 2 x 4096 (SW64)      = 8192
#define SM_V  12288                     // V[buf]: 2 x 32768 (SW128)    = 65536
#define SM_P  77824                     // P[buf]: 2 x 8192 (SW128)     = 16384
#define SM_PM 94208                     // pmax[64][4] floats           = 1024
#define SM_LS 95232                     // lsum[64][4] floats           = 1024
#define SM_LR 96256                     // lrecip[64] floats            = 256
#define SM_TOTAL 96512

// qkv_mma smem: W [buf2][hl2][4KB] = 16K, X hi [buf2][16KB] = 32K
#define QSW 0
#define QSX 16384
#define QS_TOTAL 49152

// ---------------------------------------------------------------------------
// scratch (allocation-free rule: device globals)
// ---------------------------------------------------------------------------
__device__ __half g_qh[(size_t)B_ * N_ * D_];
__device__ __half g_kh[(size_t)B_ * N_ * D_];
__device__ __half g_v [(size_t)B_ * C_ * N_];
__device__ __half g_xh[(size_t)B_ * C_ * N_];   // x fp16 [b][c][n]
__device__ __half g_wh[320 * 256];              // [Wq;Wk;Wv] split hi
__device__ __half g_wl[320 * 256];              // [Wq;Wk;Wv] split lo

__device__ __forceinline__ uint32_t smem_u32(const void* p) {
    uint32_t a;
    asm("{ .reg .u64 t; cvta.to.shared.u64 t, %1; cvt.u32.u64 %0, t; }" : "=r"(a) : "l"(p));
    return a;
}
__device__ __forceinline__ void ldsm4(uint32_t* r, uint32_t addr) {
    asm volatile("ldmatrix.sync.aligned.m8n8.x4.shared.b16 {%0,%1,%2,%3}, [%4];"
                 : "=r"(r[0]), "=r"(r[1]), "=r"(r[2]), "=r"(r[3]) : "r"(addr));
}
__device__ __forceinline__ void ldsm4t(uint32_t* r, uint32_t addr) {
    asm volatile("ldmatrix.sync.aligned.m8n8.x4.trans.shared.b16 {%0,%1,%2,%3}, [%4];"
                 : "=r"(r[0]), "=r"(r[1]), "=r"(r[2]), "=r"(r[3]) : "r"(addr));
}
__device__ __forceinline__ void mma_f16(float* c, const uint32_t* a, uint32_t b0, uint32_t b1) {
    asm volatile("mma.sync.aligned.m16n8k16.row.col.f32.f16.f16.f32 "
                 "{%0,%1,%2,%3}, {%4,%5,%6,%7}, {%8,%9}, {%0,%1,%2,%3};"
                 : "+f"(c[0]), "+f"(c[1]), "+f"(c[2]), "+f"(c[3])
                 : "r"(a[0]), "r"(a[1]), "r"(a[2]), "r"(a[3]), "r"(b0), "r"(b1));
}
__device__ __forceinline__ void cpa16(uint32_t dst, const void* src) {
    asm volatile("cp.async.cg.shared.global [%0], [%1], 16;" :: "r"(dst), "l"(src));
}
#define CP_COMMIT() asm volatile("cp.async.commit_group;" ::: "memory")
#define CP_WAIT(n)  asm volatile("cp.async.wait_group %0;" :: "n"(n) : "memory")

__device__ __forceinline__ float ex2f(float x) {
    float r; asm("ex2.approx.f32 %0, %1;" : "=f"(r) : "f"(x)); return r;
}

// swizzles: 64B rows (Q/K/W) and 128B rows (V/P)
__device__ __forceinline__ uint32_t sw64(int row, int u)  { return row * 64  + ((u ^ ((row >> 1) & 3)) << 4); }
__device__ __forceinline__ uint32_t sw128(int row, int u) { return row * 128 + ((u ^ (row & 7)) << 4); }

// ldmatrix x4 address helpers
__device__ __forceinline__ uint32_t a64(uint32_t base, int row0, int k16, int lane) {
    int lr = lane & 7, grp = lane >> 3;
    return base + sw64(row0 + lr + (grp & 1) * 8, k16 + (grp >> 1));
}
__device__ __forceinline__ uint32_t b64(uint32_t base, int row0, int k16, int lane) {
    int lr = lane & 7, grp = lane >> 3;
    return base + sw64(row0 + lr + (grp >> 1) * 8, k16 + (grp & 1));
}
__device__ __forceinline__ uint32_t a128(uint32_t base, int row0, int k16, int lane) {
    int lr = lane & 7, grp = lane >> 3;
    return base + sw128(row0 + lr + (grp & 1) * 8, k16 + (grp >> 1));
}
__device__ __forceinline__ uint32_t b128(uint32_t base, int row0, int k16, int lane) {
    int lr = lane & 7, grp = lane >> 3;
    return base + sw128(row0 + lr + (grp >> 1) * 8, k16 + (grp & 1));
}
// B-fragment (trans) from X stored [k][n] (512B rows, k-XOR swizzle on 16B units)
__device__ __forceinline__ uint32_t bxt(uint32_t base, int k0, int n0, int lane) {
    int lr = lane & 7, grp = lane >> 3;
    int k  = k0 + lr + (grp & 1) * 8;
    int un = (n0 >> 3) + (grp >> 1);
    return base + (k * 32 + (un ^ (k & 7))) * 16;
}
__device__ __forceinline__ uint32_t h2pack(float a, float b) {
    __half2 h = __floats2half2_rn(a, b);
    return *reinterpret_cast<uint32_t*>(&h);
}

// ---------------------------------------------------------------------------
// split kernel: x -> g_xh (single fp16), [Wq;Wk;Wv] -> g_wh/g_wl (hi/lo)
// ---------------------------------------------------------------------------
__global__ __launch_bounds__(256) void split_kernel(
    const float* __restrict__ x,
    const float* __restrict__ Wq, const float* __restrict__ Wk,
    const float* __restrict__ Wv)
{
    const int bid = blockIdx.x;
    const int t   = threadIdx.x;
    if (bid < 4096) {
        size_t base = (size_t)bid * 2048 + (size_t)t * 8;
        float4 v0 = *(const float4*)(x + base);
        float4 v1 = *(const float4*)(x + base + 4);
        __half h[8];
        h[0] = __float2half_rn(v0.x); h[1] = __float2half_rn(v0.y);
        h[2] = __float2half_rn(v0.z); h[3] = __float2half_rn(v0.w);
        h[4] = __float2half_rn(v1.x); h[5] = __float2half_rn(v1.y);
        h[6] = __float2half_rn(v1.z); h[7] = __float2half_rn(v1.w);
        *(uint4*)(g_xh + base) = *(uint4*)h;
    } else {
        int idx = (bid - 4096) * 2048 + t * 8;
        if (idx < 320 * 256) {
            int row = idx >> 8, col = idx & 255;
            const float* src;
            if (row < 32)       src = Wq + row * 256 + col;
            else if (row < 64)  src = Wk + (row - 32) * 256 + col;
            else                src = Wv + (row - 64) * 256 + col;
            float4 v0 = *(const float4*)(src);
            float4 v1 = *(const float4*)(src + 4);
            float vv[8] = {v0.x, v0.y, v0.z, v0.w, v1.x, v1.y, v1.z, v1.w};
            __half h[8], l[8];
#pragma unroll
            for (int i = 0; i < 8; i++) {
                h[i] = __float2half_rn(vv[i]);
                l[i] = __float2half_rn(vv[i] - __half2float(h[i]));
            }
            *(uint4*)(g_wh + idx) = *(uint4*)h;
            *(uint4*)(g_wl + idx) = *(uint4*)l;
        }
    }
}

// ---------------------------------------------------------------------------
// qkv via tensor cores: Y = W @ X + bias, 2-term fp16 (Wh·Xh + Wl·Xh).
// K rows are scaled by log2(e) in the epilogue (log2-domain softmax).
// ---------------------------------------------------------------------------
__global__ __launch_bounds__(256, 2) void qkv_mma(
    const float* __restrict__ bq, const float* __restrict__ bk,
    const float* __restrict__ bv)
{
    extern __shared__ char smem[];
    const uint32_t sb = smem_u32(smem);
    const int t    = threadIdx.x;
    const int w    = t >> 5;
    const int lane = t & 31;
    const int g    = lane >> 2;
    const int tig  = lane & 3;
    const int n0   = blockIdx.x * 256;
    const int row0 = blockIdx.y * 64;
    const int b    = blockIdx.z;
    const int mqw  = (w & 1) * 32;
    const int nw   = (w >> 1) * 64;

    {
        const int k0 = 0;
#pragma unroll
        for (int it = 0; it < 2; it++) {
            int cw = it * THREADS + t;
            int hl = cw >> 8, idx = cw & 255, r = idx >> 2, u = idx & 3;
            const __half* src = (hl ? g_wl : g_wh) + (row0 + r) * 256 + k0 + u * 8;
            cpa16(sb + QSW + hl * 4096 + sw64(r, u), src);
        }
#pragma unroll
        for (int it = 0; it < 4; it++) {
            int cx = it * THREADS + t;
            int k = cx >> 5, u = cx & 31;
            const __half* src = g_xh + ((size_t)(b * 256 + k0 + k)) * N_ + n0 + u * 8;
            cpa16(sb + QSX + (k * 32 + (u ^ (k & 7))) * 16, src);
        }
        CP_COMMIT();
    }

    float o[2][8][4];
#pragma unroll
    for (int mb = 0; mb < 2; mb++)
#pragma unroll
        for (int nb = 0; nb < 8; nb++)
#pragma unroll
            for (int r = 0; r < 4; r++) o[mb][nb][r] = 0.f;

    for (int ck = 0; ck < 8; ck++) {
        const int buf = ck & 1;
        __syncthreads();
        if (ck + 1 < 8) {
            const int k0 = (ck + 1) * 32, bn = (ck + 1) & 1;
#pragma unroll
            for (int it = 0; it < 2; it++) {
                int cw = it * THREADS + t;
                int hl = cw >> 8, idx = cw & 255, r = idx >> 2, u = idx & 3;
                const __half* src = (hl ? g_wl : g_wh) + (row0 + r) * 256 + k0 + u * 8;
                cpa16(sb + QSW + (bn * 2 + hl) * 4096 + sw64(r, u), src);
            }
#pragma unroll
            for (int it = 0; it < 4; it++) {
                int cx = it * THREADS + t;
                int k = cx >> 5, u = cx & 31;
                const __half* src = g_xh + ((size_t)(b * 256 + k0 + k)) * N_ + n0 + u * 8;
                cpa16(sb + QSX + bn * 16384 + (k * 32 + (u ^ (k & 7))) * 16, src);
            }
            CP_COMMIT();
            CP_WAIT(1);
        } else {
            CP_WAIT(0);
        }
        __syncthreads();

        const uint32_t baseWh = sb + QSW + (buf * 2 + 0) * 4096;
        const uint32_t baseWl = sb + QSW + (buf * 2 + 1) * 4096;
        const uint32_t baseXh = sb + QSX + buf * 16384;

#pragma unroll
        for (int kb = 0; kb < 2; kb++) {
            uint32_t ah[2][4], al[2][4];
            ldsm4(ah[0], a64(baseWh, mqw,      kb * 2, lane));
            ldsm4(ah[1], a64(baseWh, mqw + 16, kb * 2, lane));
            ldsm4(al[0], a64(baseWl, mqw,      kb * 2, lane));
            ldsm4(al[1], a64(baseWl, mqw + 16, kb * 2, lane));
#pragma unroll
            for (int nt = 0; nt < 4; nt++) {
                uint32_t bh[4];
                ldsm4t(bh, bxt(baseXh, kb * 16, nw + nt * 16, lane));
#pragma unroll
                for (int mb = 0; mb < 2; mb++) {
                    mma_f16(o[mb][nt * 2 + 0], ah[mb], bh[0], bh[1]);
                    mma_f16(o[mb][nt * 2 + 1], ah[mb], bh[2], bh[3]);
                    mma_f16(o[mb][nt * 2 + 0], al[mb], bh[0], bh[1]);
                    mma_f16(o[mb][nt * 2 + 1], al[mb], bh[2], bh[3]);
                }
            }
        }
    }

    if (row0 == 0) {
#pragma unroll
        for (int mb = 0; mb < 2; mb++)
#pragma unroll
            for (int hh = 0; hh < 2; hh++) {
                int rg = mqw + mb * 16 + g + hh * 8;
                const bool isq = (rg < 32);
                const int d = isq ? rg : rg - 32;
                const float bias = isq ? bq[rg] : bk[rg - 32];
                const float scale = isq ? 1.f : LOG2E;   // K in log2 domain
                __half* dh = isq ? g_qh : g_kh;
#pragma unroll
                for (int nb = 0; nb < 8; nb++)
#pragma unroll
                    for (int c2 = 0; c2 < 2; c2++) {
                        float val = (o[mb][nb][hh * 2 + c2] + bias) * scale;
                        int n = n0 + nw + nb * 8 + tig * 2 + c2;
                        dh[((size_t)b * N_ + n) * D_ + d] = __float2half_rn(val);
                    }
            }
    } else {
#pragma unroll
        for (int mb = 0; mb < 2; mb++)
#pragma unroll
            for (int hh = 0; hh < 2; hh++) {
                int c = row0 - 64 + mqw + mb * 16 + g + hh * 8;
                const float bias = bv[c];
#pragma unroll
                for (int nb = 0; nb < 8; nb++) {
                    float v0 = o[mb][nb][hh * 2 + 0] + bias;
                    float v1 = o[mb][nb][hh * 2 + 1] + bias;
                    int n = n0 + nw + nb * 8 + tig * 2;
                    *(uint32_t*)(g_v + ((size_t)b * C_ + c) * (size_t)N_ + n) = h2pack(v0, v1);
                }
            }
    }
}

// ---------------------------------------------------------------------------
// fp16 flash attention — byte-identical to the 407.6us R16 version:
// single-term QK, log2-domain softmax, pipelined PV one tile behind.
// 1 CTA per (batch, 64-q tile), 256 thr, 2 CTAs/SM.
// ---------------------------------------------------------------------------
__global__ __launch_bounds__(THREADS, 2) void attn_kernel(
    const float* __restrict__ x, const float* __restrict__ gamma_p,
    float* __restrict__ out)
{
    extern __shared__ char smem[];
    const uint32_t sb = smem_u32(smem);
    const int t    = threadIdx.x;
    const int w    = t >> 5;
    const int lane = t & 31;
    const int g    = lane >> 2;
    const int tig  = lane & 3;
    const int b    = blockIdx.y;
    const int q0   = blockIdx.x * QTILE;
    const int qg   = w & 1;
    const int sl   = w >> 1;
    const int mq   = qg * 32;

    const __half* qhp = g_qh + (size_t)b * N_ * D_;
    const __half* khp = g_kh + (size_t)b * N_ * D_;
    const __half* vp  = g_v  + (size_t)b * C_ * (size_t)N_;

    // prefetch tile 0: K group, then V group (separate commits!)
    {
        int row = t >> 2, u = t & 3;
        cpa16(sb + SM_K + sw64(row, u), khp + (size_t)row * D_ + u * 8);
    }
    CP_COMMIT();
#pragma unroll
    for (int it = 0; it < 8; it++) {
        int chunk = it * THREADS + t;
        int row = chunk >> 3, u = chunk & 7;
        cpa16(sb + SM_V + sw128(row, u), vp + (size_t)row * N_ + u * 8);
    }
    CP_COMMIT();

    // Q tile (hi only) plain load: 64 rows x 64B = 256 uint4 chunks
    {
        int row = t >> 2, u = t & 3;
        const __half* src = qhp + (size_t)(q0 + row) * D_ + u * 8;
        *(uint4*)(smem + SM_Q + sw64(row, u)) = *(const uint4*)src;
    }
    __syncthreads();

    // Q fragments (static across tiles) — hi only
    uint32_t qhf[2][2][4];
#pragma unroll
    for (int mb = 0; mb < 2; mb++)
#pragma unroll
        for (int kb = 0; kb < 2; kb++)
            ldsm4(qhf[mb][kb], a64(sb + SM_Q, mq + mb * 16, kb * 2, lane));

    float o[2][8][4];
#pragma unroll
    for (int mb = 0; mb < 2; mb++)
#pragma unroll
        for (int nb = 0; nb < 8; nb++)
#pragma unroll
            for (int r = 0; r < 4; r++) o[mb][nb][r] = 0.f;

    float lacc[2][2] = {{0.f, 0.f}, {0.f, 0.f}};
    float mold[2][2];

    // ======================= peeled tile 0 =======================
    {
        CP_WAIT(1);          // K(0) done (V(0) may be in flight)
        __syncthreads();
        // prefetch K(1)
        {
            int row = t >> 2, u = t & 3;
            cpa16(sb + SM_K + 4096 + sw64(row, u), khp + (size_t)(KTILE + row) * D_ + u * 8);
        }
        CP_COMMIT();

        // S(0): single term
        float s[2][2][4];
#pragma unroll
        for (int mb = 0; mb < 2; mb++)
#pragma unroll
            for (int nb = 0; nb < 2; nb++)
#pragma unroll
                for (int r = 0; r < 4; r++) s[mb][nb][r] = 0.f;
#pragma unroll
        for (int kb = 0; kb < 2; kb++) {
            uint32_t khf[4];
            ldsm4(khf, b64(sb + SM_K, sl * 16, kb * 2, lane));
#pragma unroll
            for (int mb = 0; mb < 2; mb++)
#pragma unroll
                for (int nb = 0; nb < 2; nb++)
                    mma_f16(s[mb][nb], qhf[mb][kb], khf[nb * 2], khf[nb * 2 + 1]);
        }
        // max
        float mloc[2][2];
#pragma unroll
        for (int mb = 0; mb < 2; mb++) {
            mloc[mb][0] = fmaxf(fmaxf(s[mb][0][0], s[mb][0][1]), fmaxf(s[mb][1][0], s[mb][1][1]));
            mloc[mb][1] = fmaxf(fmaxf(s[mb][0][2], s[mb][0][3]), fmaxf(s[mb][1][2], s[mb][1][3]));
        }
#pragma unroll
        for (int mb = 0; mb < 2; mb++)
#pragma unroll
            for (int hf = 0; hf < 2; hf++) {
                float v = mloc[mb][hf];
                v = fmaxf(v, __shfl_xor_sync(0xffffffffu, v, 1));
                v = fmaxf(v, __shfl_xor_sync(0xffffffffu, v, 2));
                mloc[mb][hf] = v;
            }
        if (tig == 0) {
#pragma unroll
            for (int mb = 0; mb < 2; mb++)
#pragma unroll
                for (int hf = 0; hf < 2; hf++)
                    *(float*)(smem + SM_PM + (mq + mb * 16 + g + hf * 8) * 16 + sl * 4) = mloc[mb][hf];
        }
        __syncthreads();
#pragma unroll
        for (int mb = 0; mb < 2; mb++)
#pragma unroll
            for (int hf = 0; hf < 2; hf++) {
                int row = mq + mb * 16 + g + hf * 8;
                float4 pm = *(const float4*)(smem + SM_PM + row * 16);
                mold[mb][hf] = fmaxf(fmaxf(pm.x, pm.y), fmaxf(pm.z, pm.w));
            }
        // softmax(0) -> P buf 0 (log2 domain)
#pragma unroll
        for (int mb = 0; mb < 2; mb++)
#pragma unroll
            for (int nb = 0; nb < 2; nb++) {
                float e0 = ex2f(s[mb][nb][0] - mold[mb][0]);
                float e1 = ex2f(s[mb][nb][1] - mold[mb][0]);
                float e2 = ex2f(s[mb][nb][2] - mold[mb][1]);
                float e3 = ex2f(s[mb][nb][3] - mold[mb][1]);
                __half2 h01 = __floats2half2_rn(e0, e1);
                __half2 h23 = __floats2half2_rn(e2, e3);
                float2 f01 = __half22float2(h01), f23 = __half22float2(h23);
                lacc[mb][0] += f01.x + f01.y;
                lacc[mb][1] += f23.x + f23.y;
                int r0 = mq + mb * 16 + g;
                int u  = sl * 2 + nb;
                *(uint32_t*)(smem + SM_P + sw128(r0,     u) + tig * 4) = *(uint32_t*)&h01;
                *(uint32_t*)(smem + SM_P + sw128(r0 + 8, u) + tig * 4) = *(uint32_t*)&h23;
            }
        __syncthreads();   // P(0) visible
        // prefetch V(1)
#pragma unroll
        for (int it = 0; it < 8; it++) {
            int chunk = it * THREADS + t;
            int row = chunk >> 3, u = chunk & 7;
            cpa16(sb + SM_V + 32768 + sw128(row, u), vp + (size_t)row * N_ + KTILE + u * 8);
        }
        CP_COMMIT();
    }

    // ======================= main loop t=1..63 =======================
    for (int tile = 1; tile < NTILES; tile++) {
        const int buf = tile & 1;   // K/V/P write buffer; read side uses buf^1
        CP_WAIT(1);                 // K(t) + V(t-1) ready (V(t) may be in flight)
        __syncthreads();

        if (tile + 1 < NTILES) {
            const int jn = (tile + 1) * KTILE, bn = (tile + 1) & 1;
            int row = t >> 2, u = t & 3;
            cpa16(sb + SM_K + bn * 4096 + sw64(row, u), khp + (size_t)(jn + row) * D_ + u * 8);
        }
        CP_COMMIT();   // K group committed every iteration (possibly empty) to keep order

        // ---- S(t) = Q K^T : single term ----
        float s[2][2][4];
#pragma unroll
        for (int mb = 0; mb < 2; mb++)
#pragma unroll
            for (int nb = 0; nb < 2; nb++)
#pragma unroll
                for (int r = 0; r < 4; r++) s[mb][nb][r] = 0.f;
#pragma unroll
        for (int kb = 0; kb < 2; kb++) {
            uint32_t khf[4];
            ldsm4(khf, b64(sb + SM_K + buf * 4096, sl * 16, kb * 2, lane));
#pragma unroll
            for (int mb = 0; mb < 2; mb++)
#pragma unroll
                for (int nb = 0; nb < 2; nb++)
                    mma_f16(s[mb][nb], qhf[mb][kb], khf[nb * 2], khf[nb * 2 + 1]);
        }

        // ---- row max exchange ----
        float mloc[2][2];
#pragma unroll
        for (int mb = 0; mb < 2; mb++) {
            mloc[mb][0] = fmaxf(fmaxf(s[mb][0][0], s[mb][0][1]), fmaxf(s[mb][1][0], s[mb][1][1]));
            mloc[mb][1] = fmaxf(fmaxf(s[mb][0][2], s[mb][0][3]), fmaxf(s[mb][1][2], s[mb][1][3]));
        }
#pragma unroll
        for (int mb = 0; mb < 2; mb++)
#pragma unroll
            for (int hf = 0; hf < 2; hf++) {
                float v = mloc[mb][hf];
                v = fmaxf(v, __shfl_xor_sync(0xffffffffu, v, 1));
                v = fmaxf(v, __shfl_xor_sync(0xffffffffu, v, 2));
                mloc[mb][hf] = v;
            }
        if (tig == 0) {
#pragma unroll
            for (int mb = 0; mb < 2; mb++)
#pragma unroll
                for (int hf = 0; hf < 2; hf++)
                    *(float*)(smem + SM_PM + (mq + mb * 16 + g + hf * 8) * 16 + sl * 4) = mloc[mb][hf];
        }
        __syncthreads();

        // ---- alpha(t) (log2 domain) ----
        float al[2][2];
#pragma unroll
        for (int mb = 0; mb < 2; mb++)
#pragma unroll
            for (int hf = 0; hf < 2; hf++) {
                int row = mq + mb * 16 + g + hf * 8;
                float4 pm = *(const float4*)(smem + SM_PM + row * 16);
                float mt = fmaxf(fmaxf(pm.x, pm.y), fmaxf(pm.z, pm.w));
                float mn = fmaxf(mold[mb][hf], mt);
                al[mb][hf] = ex2f(mold[mb][hf] - mn);
                mold[mb][hf] = mn;
            }

        // ---- interleaved: PV(t-1) MMAs + softmax(t) exps (independent pipes)
        float lsum[2][2] = {{0.f, 0.f}, {0.f, 0.f}};
        const uint32_t pR = sb + SM_P + (buf ^ 1) * 8192;
        const uint32_t vR = sb + SM_V + (buf ^ 1) * 32768;
        const int pWo = SM_P + buf * 8192;
#pragma unroll
        for (int kb = 0; kb < 4; kb++) {
            uint32_t phf[2][4];
            ldsm4(phf[0], a128(pR, mq,      kb * 2, lane));
            ldsm4(phf[1], a128(pR, mq + 16, kb * 2, lane));
#pragma unroll
            for (int nb2 = 0; nb2 < 4; nb2++) {
                uint32_t vhf[4];
                ldsm4(vhf, b128(vR, sl * 64 + nb2 * 16, kb * 2, lane));
                mma_f16(o[0][nb2 * 2 + 0], phf[0], vhf[0], vhf[1]);
                mma_f16(o[0][nb2 * 2 + 1], phf[0], vhf[2], vhf[3]);
                mma_f16(o[1][nb2 * 2 + 0], phf[1], vhf[0], vhf[1]);
                mma_f16(o[1][nb2 * 2 + 1], phf[1], vhf[2], vhf[3]);
            }
            // softmax chunk (mb,nb) = (kb>>1, kb&1), log2 domain
            {
                const int mb = kb >> 1, nb = kb & 1;
                float e0 = ex2f(s[mb][nb][0] - mold[mb][0]);
                float e1 = ex2f(s[mb][nb][1] - mold[mb][0]);
                float e2 = ex2f(s[mb][nb][2] - mold[mb][1]);
                float e3 = ex2f(s[mb][nb][3] - mold[mb][1]);
                __half2 h01 = __floats2half2_rn(e0, e1);
                __half2 h23 = __floats2half2_rn(e2, e3);
                float2 f01 = __half22float2(h01), f23 = __half22float2(h23);
                lsum[mb][0] += f01.x + f01.y;
                lsum[mb][1] += f23.x + f23.y;
                int r0 = mq + mb * 16 + g;
                int u  = sl * 2 + nb;
                *(uint32_t*)(smem + pWo + sw128(r0,     u) + tig * 4) = *(uint32_t*)&h01;
                *(uint32_t*)(smem + pWo + sw128(r0 + 8, u) + tig * 4) = *(uint32_t*)&h23;
            }
        }
        // rescale to frame m(t): O = (O + PV(t-1)) * alpha
#pragma unroll
        for (int mb = 0; mb < 2; mb++)
#pragma unroll
            for (int nb = 0; nb < 8; nb++) {
                o[mb][nb][0] *= al[mb][0]; o[mb][nb][1] *= al[mb][0];
                o[mb][nb][2] *= al[mb][1]; o[mb][nb][3] *= al[mb][1];
            }
#pragma unroll
        for (int mb = 0; mb < 2; mb++)
#pragma unroll
            for (int hf = 0; hf < 2; hf++)
                lacc[mb][hf] = lacc[mb][hf] * al[mb][hf] + lsum[mb][hf];

        __syncthreads();   // PV(t-1) done (V(t-1) free), P(t) visible

        if (tile + 1 < NTILES) {
            const int jn = (tile + 1) * KTILE, bn = (tile + 1) & 1;
#pragma unroll
            for (int it = 0; it < 8; it++) {
                int chunk = it * THREADS + t;
                int row = chunk >> 3, u = chunk & 7;
                cpa16(sb + SM_V + bn * 32768 + sw128(row, u), vp + (size_t)row * N_ + jn + u * 8);
            }
        }
        CP_COMMIT();   // V group committed every iteration (possibly empty)
    }

    // ======================= drain PV(63) =======================
    CP_WAIT(0);
    __syncthreads();
    {
        const int buf = (NTILES - 1) & 1;   // = 1
        const uint32_t pR = sb + SM_P + buf * 8192;
        const uint32_t vR = sb + SM_V + buf * 32768;
#pragma unroll
        for (int kb = 0; kb < 4; kb++) {
            uint32_t phf[2][4];
            ldsm4(phf[0], a128(pR, mq,      kb * 2, lane));
            ldsm4(phf[1], a128(pR, mq + 16, kb * 2, lane));
#pragma unroll
            for (int nb2 = 0; nb2 < 4; nb2++) {
                uint32_t vhf[4];
                ldsm4(vhf, b128(vR, sl * 64 + nb2 * 16, kb * 2, lane));
                mma_f16(o[0][nb2 * 2 + 0], phf[0], vhf[0], vhf[1]);
                mma_f16(o[0][nb2 * 2 + 1], phf[0], vhf[2], vhf[3]);
                mma_f16(o[1][nb2 * 2 + 0], phf[1], vhf[0], vhf[1]);
                mma_f16(o[1][nb2 * 2 + 1], phf[1], vhf[2], vhf[3]);
            }
        }
    }

    // ---- l reduction: quad shuffle, then cross-warp via smem ----
#pragma unroll
    for (int mb = 0; mb < 2; mb++)
#pragma unroll
        for (int hf = 0; hf < 2; hf++) {
            float v = lacc[mb][hf];
            v += __shfl_xor_sync(0xffffffffu, v, 1);
            v += __shfl_xor_sync(0xffffffffu, v, 2);
            lacc[mb][hf] = v;
        }
    if (tig == 0) {
#pragma unroll
        for (int mb = 0; mb < 2; mb++)
#pragma unroll
            for (int hf = 0; hf < 2; hf++) {
                int row = mq + mb * 16 + g + hf * 8;
                *(float*)(smem + SM_LS + (row * 4 + sl) * 4) = lacc[mb][hf];
            }
    }
    __syncthreads();
    if (t < 64) {
        const float* ls = (const float*)(smem + SM_LS) + t * 4;
        *(float*)(smem + SM_LR + t * 4) = 1.f / (ls[0] + ls[1] + ls[2] + ls[3]);
    }
    __syncthreads();

    // ---- epilogue: out = gamma * O / l + x ----
    {
        const float gma = *gamma_p;
#pragma unroll
        for (int mb = 0; mb < 2; mb++) {
            int r0 = mq + mb * 16 + g;
            int r1 = r0 + 8;
            float li0 = *(const float*)(smem + SM_LR + r0 * 4);
            float li1 = *(const float*)(smem + SM_LR + r1 * 4);
            int i0 = q0 + r0, i1 = q0 + r1;
#pragma unroll
            for (int nb = 0; nb < 8; nb++) {
                int c = sl * 64 + nb * 8 + tig * 2;
                size_t base0 = ((size_t)b * C_ + c) * (size_t)N_;
                size_t base1 = base0 + N_;
                out[base0 + i0] = gma * (o[mb][nb][0] * li0) + x[base0 + i0];
                out[base1 + i0] = gma * (o[mb][nb][1] * li0) + x[base1 + i0];
                out[base0 + i1] = gma * (o[mb][nb][2] * li1) + x[base0 + i1];
                out[base1 + i1] = gma * (o[mb][nb][3] * li1) + x[base1 + i1];
            }
        }
    }
}

extern "C" void kernel_launch(void* const* d_in, const int* in_sizes, int n_in,
                              void* d_out, int out_size) {
    const float* x  = (const float*)d_in[0];
    const float* Wq = (const float*)d_in[1];
    const float* bq = (const float*)d_in[2];
    const float* Wk = (const float*)d_in[3];
    const float* bk = (const float*)d_in[4];
    const float* Wv = (const float*)d_in[5];
    const float* bv = (const float*)d_in[6];
    const float* gm = (const float*)d_in[7];
    float* out = (float*)d_out;

    cudaFuncSetAttribute(qkv_mma, cudaFuncAttributeMaxDynamicSharedMemorySize, QS_TOTAL);
    cudaFuncSetAttribute(attn_kernel, cudaFuncAttributeMaxDynamicSharedMemorySize, SM_TOTAL);

    split_kernel<<<4136, 256>>>(x, Wq, Wk, Wv);
    qkv_mma<<<dim3(16, 5, 8), 256, QS_TOTAL>>>(bq, bk, bv);
    attn_kernel<<<dim3(N_ / QTILE, B_), THREADS, SM_TOTAL>>>(x, gm, out);
}